// round 8
// baseline (speedup 1.0000x reference)
#include <cuda_runtime.h>
#include <cuda_fp16.h>

// ---------------------------------------------------------------------------
// MSDeformAttention  (bs=8, Lq=Lv=5440, D=256, 8 heads x 32, 4 levels x 4 pts)
//
//   1) V      = value @ Wv + bv        (tf32 MMA, pipelined, -> fp16 g_Vh)
//   2) OFF/AW = query @ [Woff|Wa]      (single fused tf32 MMA launch)
//   3) AW     = softmax16(softmax128(AWL))
//   4) MID    = bilinear-gather, 3-phase (addr/cw -> 8x LDG.128 -> acc)
//   5) out    = MID @ Wout + bout      (tf32 MMA, pipelined)
// ---------------------------------------------------------------------------

#define LQ     5440
#define BSZ    8
#define NH     8
#define DH     32
#define DMODEL 256
#define MROWS  (BSZ * LQ)          // 43520
#define KDIM   256

// scratch (static device globals: allocation-free)
__device__ __half g_Vh [BSZ * NH * LQ * DH];    // [b][h][pos][c]  fp16
__device__ float  g_off[(size_t)MROWS * DMODEL];
__device__ float  g_aw [(size_t)MROWS * 128];
__device__ float  g_mid[(size_t)MROWS * DMODEL];

// tf32 round (rna); returns the b32 bit pattern (cvt.rna.tf32 needs .b32 dst).
__device__ __forceinline__ unsigned f2tf32(float x) {
    unsigned y;
    asm("cvt.rna.tf32.f32 %0, %1;" : "=r"(y) : "f"(x));
    return y;
}

// ---------------------------------------------------------------------------
// Shared GEMM body: C[M,N] = A[M,256] @ B[256,N] + bias[N]
// Block tile 128x128, BK=16, 256 threads = 8 warps (4m x 2n), warp tile 32x64.
// Software-pipelined: next k-tile is prefetched into registers before the MMA
// block so global latency hides under the 128 MMAs.
// mode 0: row-major fp32 C.   mode 1: permuted fp16 write into g_Vh.
// ---------------------------------------------------------------------------
__device__ __forceinline__ void gemm_body(
    const float* __restrict__ A, const float* __restrict__ B,
    const float* __restrict__ bias, float* __restrict__ C,
    int N, int m0, int n0, int mode)
{
    __shared__ unsigned As[16][136];   // [k][m]  (tf32 bit patterns)
    __shared__ unsigned Bs[16][136];   // [k][n]

    const int tid  = threadIdx.x;
    const int lane = tid & 31;
    const int warp = tid >> 5;
    const int gid  = lane >> 2;     // 0..7
    const int tig  = lane & 3;      // 0..3
    const int wm   = (warp >> 1) * 32;
    const int wn   = (warp & 1) * 64;

    const int la_row = tid >> 1;
    const int la_cg  = (tid & 1) * 8;
    const int lb_row = tid >> 4;
    const int lb_c4  = (tid & 15) * 4;

    const float* Ap = A + (size_t)(m0 + la_row) * KDIM + la_cg;
    const float* Bp = B + (size_t)lb_row * N + n0 + lb_c4;

    float acc[2][8][4];
#pragma unroll
    for (int mt = 0; mt < 2; mt++)
#pragma unroll
        for (int nt = 0; nt < 8; nt++)
#pragma unroll
            for (int r = 0; r < 4; r++) acc[mt][nt][r] = 0.0f;

    // prologue: load first k-tile into registers
    float4 av0 = *(const float4*)(Ap);
    float4 av1 = *(const float4*)(Ap + 4);
    float4 bv0 = *(const float4*)(Bp);
    float4 bv1 = *(const float4*)(Bp + 64);

    for (int k0 = 0; k0 < KDIM; k0 += 16) {
        // store current regs to smem (tf32 convert)
        As[la_cg + 0][la_row] = f2tf32(av0.x);
        As[la_cg + 1][la_row] = f2tf32(av0.y);
        As[la_cg + 2][la_row] = f2tf32(av0.z);
        As[la_cg + 3][la_row] = f2tf32(av0.w);
        As[la_cg + 4][la_row] = f2tf32(av1.x);
        As[la_cg + 5][la_row] = f2tf32(av1.y);
        As[la_cg + 6][la_row] = f2tf32(av1.z);
        As[la_cg + 7][la_row] = f2tf32(av1.w);
        Bs[lb_row][lb_c4 + 0]  = f2tf32(bv0.x);
        Bs[lb_row][lb_c4 + 1]  = f2tf32(bv0.y);
        Bs[lb_row][lb_c4 + 2]  = f2tf32(bv0.z);
        Bs[lb_row][lb_c4 + 3]  = f2tf32(bv0.w);
        Bs[lb_row][lb_c4 + 64] = f2tf32(bv1.x);
        Bs[lb_row][lb_c4 + 65] = f2tf32(bv1.y);
        Bs[lb_row][lb_c4 + 66] = f2tf32(bv1.z);
        Bs[lb_row][lb_c4 + 67] = f2tf32(bv1.w);
        __syncthreads();

        // prefetch next k-tile while computing
        if (k0 + 16 < KDIM) {
            Ap += 16;
            Bp += (size_t)16 * N;
            av0 = *(const float4*)(Ap);
            av1 = *(const float4*)(Ap + 4);
            bv0 = *(const float4*)(Bp);
            bv1 = *(const float4*)(Bp + 64);
        }

#pragma unroll
        for (int ks = 0; ks < 16; ks += 8) {
            unsigned a[2][4], b[8][2];
#pragma unroll
            for (int mt = 0; mt < 2; mt++) {
                const int mb = wm + mt * 16;
                a[mt][0] = As[ks + tig    ][mb + gid    ];
                a[mt][1] = As[ks + tig    ][mb + gid + 8];
                a[mt][2] = As[ks + tig + 4][mb + gid    ];
                a[mt][3] = As[ks + tig + 4][mb + gid + 8];
            }
#pragma unroll
            for (int nt = 0; nt < 8; nt++) {
                const int nb = wn + nt * 8 + gid;
                b[nt][0] = Bs[ks + tig    ][nb];
                b[nt][1] = Bs[ks + tig + 4][nb];
            }
#pragma unroll
            for (int mt = 0; mt < 2; mt++)
#pragma unroll
                for (int nt = 0; nt < 8; nt++) {
                    asm volatile(
                        "mma.sync.aligned.m16n8k8.row.col.f32.tf32.tf32.f32 "
                        "{%0,%1,%2,%3}, {%4,%5,%6,%7}, {%8,%9}, {%0,%1,%2,%3};"
                        : "+f"(acc[mt][nt][0]), "+f"(acc[mt][nt][1]),
                          "+f"(acc[mt][nt][2]), "+f"(acc[mt][nt][3])
                        : "r"(a[mt][0]), "r"(a[mt][1]), "r"(a[mt][2]), "r"(a[mt][3]),
                          "r"(b[nt][0]), "r"(b[nt][1]));
                }
        }
        __syncthreads();
    }

    // epilogue
#pragma unroll
    for (int mt = 0; mt < 2; mt++) {
#pragma unroll
        for (int rr = 0; rr < 2; rr++) {
            const int m = m0 + wm + mt * 16 + gid + rr * 8;
            const int bb  = m / LQ;
            const int pos = m - bb * LQ;
#pragma unroll
            for (int nt = 0; nt < 8; nt++) {
                const int n = n0 + wn + nt * 8 + tig * 2;
                float2 v;
                v.x = acc[mt][nt][rr * 2 + 0] + bias[n];
                v.y = acc[mt][nt][rr * 2 + 1] + bias[n + 1];
                if (mode == 0) {
                    *(float2*)&C[(size_t)m * N + n] = v;
                } else {
                    const int h = n >> 5;
                    const int c = n & 31;   // even
                    __half2 hv = __floats2half2_rn(v.x, v.y);
                    *(__half2*)&g_Vh[(((size_t)(bb * NH + h)) * LQ + pos) * DH + c] = hv;
                }
            }
        }
    }
}

// generic GEMM kernel (used for V and final output)
__global__ __launch_bounds__(256) void tf32gemm(
    const float* __restrict__ A, const float* __restrict__ B,
    const float* __restrict__ bias, float* __restrict__ C,
    int N, int mode)
{
    gemm_body(A, B, bias, C, N, blockIdx.y * 128, blockIdx.x * 128, mode);
}

// fused OFF + AW GEMM: grid.x = 3.  Blocks 0,1 -> query@Woff -> g_off (N=256);
// block 2 -> query@Wa -> g_aw (N=128).
__global__ __launch_bounds__(256) void tf32gemm_offaw(
    const float* __restrict__ A,
    const float* __restrict__ Woff, const float* __restrict__ boff,
    const float* __restrict__ Wa,   const float* __restrict__ ba)
{
    const int m0 = blockIdx.y * 128;
    if (blockIdx.x < 2) {
        gemm_body(A, Woff, boff, g_off, 256, m0, blockIdx.x * 128, 0);
    } else {
        gemm_body(A, Wa, ba, g_aw, 128, m0, 0, 0);
    }
}

// ---------------------------------------------------------------------------
// Double softmax (unchanged).
// ---------------------------------------------------------------------------
__global__ __launch_bounds__(256) void softmax2_kernel(float* __restrict__ buf)
{
    const int warp = threadIdx.x >> 5;
    const int lane = threadIdx.x & 31;
    const int row  = blockIdx.x * 8 + warp;
    float* p = buf + (size_t)row * 128 + lane * 4;

    float4 v = *(const float4*)p;

    float vm = fmaxf(fmaxf(v.x, v.y), fmaxf(v.z, v.w));
#pragma unroll
    for (int o = 16; o; o >>= 1) vm = fmaxf(vm, __shfl_xor_sync(~0u, vm, o));
    float e0 = expf(v.x - vm), e1 = expf(v.y - vm);
    float e2 = expf(v.z - vm), e3 = expf(v.w - vm);
    float s = e0 + e1 + e2 + e3;
#pragma unroll
    for (int o = 16; o; o >>= 1) s += __shfl_xor_sync(~0u, s, o);
    const float inv = 1.0f / s;
    const float t0 = e0 * inv, t1 = e1 * inv, t2 = e2 * inv, t3 = e3 * inv;

    float gm = fmaxf(fmaxf(t0, t1), fmaxf(t2, t3));
    gm = fmaxf(gm, __shfl_xor_sync(~0u, gm, 1));
    gm = fmaxf(gm, __shfl_xor_sync(~0u, gm, 2));
    float f0 = expf(t0 - gm), f1 = expf(t1 - gm);
    float f2 = expf(t2 - gm), f3 = expf(t3 - gm);
    float gs = f0 + f1 + f2 + f3;
    gs += __shfl_xor_sync(~0u, gs, 1);
    gs += __shfl_xor_sync(~0u, gs, 2);
    const float ginv = 1.0f / gs;

    float4 o4;
    o4.x = f0 * ginv; o4.y = f1 * ginv; o4.z = f2 * ginv; o4.w = f3 * ginv;
    *(float4*)p = o4;
}

// ---------------------------------------------------------------------------
// Sampling v3: three-phase for MLP=8.
// Warp h handles head h of query bq.  Lane = (unit u = lane>>2, quarter q).
// Pass i: unit u -> (point 2i+(u>>2), corner u&3); level l = i>>1 uniform.
// Phase A: compute all 8 (ptr, cw).  Phase B: 8 back-to-back LDG.128.
// Phase C: accumulate.  Tail: shfl reduce (4,8,16), lanes 0-3 write.
// ---------------------------------------------------------------------------
__global__ __launch_bounds__(256, 2) void msdeform_sample_kernel(
    const float* __restrict__ refpts)
{
    const int bq   = blockIdx.x;
    const int b    = bq / LQ;
    const int h    = threadIdx.x >> 5;
    const int lane = threadIdx.x & 31;
    const int u    = lane >> 2;       // unit 0..7
    const int q    = lane & 3;        // channel quarter

    const int starts[4] = {0, 4096, 5120, 5376};
    const int sizes [4] = {64, 32, 16, 8};

    const float* offp = g_off + (size_t)bq * 256 + h * 32;  // [pidx*2 + xy]
    const float* awp  = g_aw  + (size_t)bq * 128 + h * 16;  // [pidx]
    const float* refp = refpts + (size_t)bq * 8;
    const __half* vbase = g_Vh + ((size_t)(b * NH + h)) * LQ * DH;

    const int cidx = u & 3;
    const int psel = u >> 2;

    // Phase A: addresses + combined weights
    const __half* ptrv[8];
    float cwv[8];
#pragma unroll
    for (int i = 0; i < 8; i++) {
        const int l     = i >> 1;
        const int S     = sizes[l];
        const int start = starts[l];
        const float inv_fs = 1.0f / (float)S;   // exact (power of 2)

        const int pidx = i * 2 + psel;

        const float rx = refp[l * 2 + 0];
        const float ry = refp[l * 2 + 1];
        const float ox = offp[pidx * 2 + 0];
        const float oy = offp[pidx * 2 + 1];
        const float w  = awp[pidx];

        const float cx = rx + ox * inv_fs;
        const float cy = ry + oy * inv_fs;
        const float x = 0.5f * ((cx + 1.0f) * (float)(S - 2));
        const float y = 0.5f * ((cy + 1.0f) * (float)(S - 2));

        const int x0 = (int)floorf(x);
        const int y0 = (int)floorf(y);
        const int x0c = min(max(x0, 0),     S - 1);
        const int x1c = min(max(x0 + 1, 0), S - 1);
        const int y0c = min(max(y0, 0),     S - 1);
        const int y1c = min(max(y0 + 1, 0), S - 1);
        const float x0f = (float)x0c, x1f = (float)x1c;
        const float y0f = (float)y0c, y1f = (float)y1c;

        const int   xi = (cidx & 2) ? x1c : x0c;
        const int   yi = (cidx & 1) ? y1c : y0c;
        const float wx = (cidx & 2) ? (x - x0f) : (x1f - x);
        const float wy = (cidx & 1) ? (y - y0f) : (y1f - y);

        cwv[i]  = w * wx * wy;
        ptrv[i] = vbase + ((size_t)(start + yi * S + xi)) * DH + q * 8;
    }

    // Phase B: 8 independent LDG.128
    uint4 hv[8];
#pragma unroll
    for (int i = 0; i < 8; i++) hv[i] = __ldg((const uint4*)ptrv[i]);

    // Phase C: accumulate
    float acc[8];
#pragma unroll
    for (int j = 0; j < 8; j++) acc[j] = 0.0f;
#pragma unroll
    for (int i = 0; i < 8; i++) {
        const float cw = cwv[i];
        const float2 f0 = __half22float2(*(const __half2*)&hv[i].x);
        const float2 f1 = __half22float2(*(const __half2*)&hv[i].y);
        const float2 f2 = __half22float2(*(const __half2*)&hv[i].z);
        const float2 f3 = __half22float2(*(const __half2*)&hv[i].w);
        acc[0] = fmaf(cw, f0.x, acc[0]);
        acc[1] = fmaf(cw, f0.y, acc[1]);
        acc[2] = fmaf(cw, f1.x, acc[2]);
        acc[3] = fmaf(cw, f1.y, acc[3]);
        acc[4] = fmaf(cw, f2.x, acc[4]);
        acc[5] = fmaf(cw, f2.y, acc[5]);
        acc[6] = fmaf(cw, f3.x, acc[6]);
        acc[7] = fmaf(cw, f3.y, acc[7]);
    }

    // reduce across the 8 units (lanes q, q+4, ..., q+28)
#pragma unroll
    for (int m = 4; m <= 16; m <<= 1)
#pragma unroll
        for (int j = 0; j < 8; j++)
            acc[j] += __shfl_xor_sync(~0u, acc[j], m);

    if (u == 0) {
        float* dst = g_mid + (size_t)bq * 256 + h * 32 + q * 8;
        *(float4*)(dst + 0) = make_float4(acc[0], acc[1], acc[2], acc[3]);
        *(float4*)(dst + 4) = make_float4(acc[4], acc[5], acc[6], acc[7]);
    }
}

// ---------------------------------------------------------------------------
// launch
// ---------------------------------------------------------------------------
extern "C" void kernel_launch(void* const* d_in, const int* in_sizes, int n_in,
                              void* d_out, int out_size)
{
    const float* query = (const float*)d_in[0];
    const float* value = (const float*)d_in[1];
    const float* refp  = (const float*)d_in[2];
    const float* Wv    = (const float*)d_in[3];
    const float* bv    = (const float*)d_in[4];
    const float* Woff  = (const float*)d_in[5];
    const float* boff  = (const float*)d_in[6];
    const float* Wa    = (const float*)d_in[7];
    const float* ba    = (const float*)d_in[8];
    const float* Wout  = (const float*)d_in[9];
    const float* bout  = (const float*)d_in[10];
    float* out = (float*)d_out;

    float *pAw, *pMid;
    cudaGetSymbolAddress((void**)&pAw,  g_aw);
    cudaGetSymbolAddress((void**)&pMid, g_mid);

    const dim3 gN256(2, MROWS / 128);   // (2, 340)
    const dim3 gOffAw(3, MROWS / 128);  // (3, 340)

    tf32gemm<<<gN256, 256>>>(value, Wv, bv, /*unused in mode1*/ pMid, 256, 1);
    tf32gemm_offaw<<<gOffAw, 256>>>(query, Woff, boff, Wa, ba);
    softmax2_kernel<<<MROWS / 8, 256>>>(pAw);
    msdeform_sample_kernel<<<MROWS, 256>>>(refp);
    tf32gemm<<<gN256, 256>>>(pMid, Wout, bout, out, 256, 0);
}

// round 9
// speedup vs baseline: 1.1273x; 1.1273x over previous
#include <cuda_runtime.h>
#include <cuda_fp16.h>

// ---------------------------------------------------------------------------
// MSDeformAttention  (bs=8, Lq=Lv=5440, D=256, 8 heads x 32, 4 levels x 4 pts)
//
//   1) V      = value @ Wv + bv        (tf32 MMA, pipelined, -> fp16 g_Vh)
//   2) OFF/AW = query @ [Woff|Wa]      (single fused tf32 MMA launch)
//   3) AW     = softmax16(softmax128(AWL))
//   4) MID    = bilinear-gather v4 (32-bit offsets, 2x4 load groups, occ 3)
//   5) out    = MID @ Wout + bout      (tf32 MMA, pipelined)
// ---------------------------------------------------------------------------

#define LQ     5440
#define BSZ    8
#define NH     8
#define DH     32
#define DMODEL 256
#define MROWS  (BSZ * LQ)          // 43520
#define KDIM   256

// scratch (static device globals: allocation-free)
__device__ __half g_Vh [BSZ * NH * LQ * DH];    // [b][h][pos][c]  fp16
__device__ float  g_off[(size_t)MROWS * DMODEL];
__device__ float  g_aw [(size_t)MROWS * 128];
__device__ float  g_mid[(size_t)MROWS * DMODEL];

// tf32 round (rna); returns the b32 bit pattern (cvt.rna.tf32 needs .b32 dst).
__device__ __forceinline__ unsigned f2tf32(float x) {
    unsigned y;
    asm("cvt.rna.tf32.f32 %0, %1;" : "=r"(y) : "f"(x));
    return y;
}

// ---------------------------------------------------------------------------
// Shared GEMM body: C[M,N] = A[M,256] @ B[256,N] + bias[N]
// Block tile 128x128, BK=16, 256 threads = 8 warps (4m x 2n), warp tile 32x64.
// Software-pipelined (register prefetch of next k-tile).
// mode 0: row-major fp32 C.   mode 1: permuted fp16 write into g_Vh.
// ---------------------------------------------------------------------------
__device__ __forceinline__ void gemm_body(
    const float* __restrict__ A, const float* __restrict__ B,
    const float* __restrict__ bias, float* __restrict__ C,
    int N, int m0, int n0, int mode)
{
    __shared__ unsigned As[16][136];   // [k][m]  (tf32 bit patterns)
    __shared__ unsigned Bs[16][136];   // [k][n]

    const int tid  = threadIdx.x;
    const int lane = tid & 31;
    const int warp = tid >> 5;
    const int gid  = lane >> 2;     // 0..7
    const int tig  = lane & 3;      // 0..3
    const int wm   = (warp >> 1) * 32;
    const int wn   = (warp & 1) * 64;

    const int la_row = tid >> 1;
    const int la_cg  = (tid & 1) * 8;
    const int lb_row = tid >> 4;
    const int lb_c4  = (tid & 15) * 4;

    const float* Ap = A + (size_t)(m0 + la_row) * KDIM + la_cg;
    const float* Bp = B + (size_t)lb_row * N + n0 + lb_c4;

    float acc[2][8][4];
#pragma unroll
    for (int mt = 0; mt < 2; mt++)
#pragma unroll
        for (int nt = 0; nt < 8; nt++)
#pragma unroll
            for (int r = 0; r < 4; r++) acc[mt][nt][r] = 0.0f;

    float4 av0 = *(const float4*)(Ap);
    float4 av1 = *(const float4*)(Ap + 4);
    float4 bv0 = *(const float4*)(Bp);
    float4 bv1 = *(const float4*)(Bp + 64);

    for (int k0 = 0; k0 < KDIM; k0 += 16) {
        As[la_cg + 0][la_row] = f2tf32(av0.x);
        As[la_cg + 1][la_row] = f2tf32(av0.y);
        As[la_cg + 2][la_row] = f2tf32(av0.z);
        As[la_cg + 3][la_row] = f2tf32(av0.w);
        As[la_cg + 4][la_row] = f2tf32(av1.x);
        As[la_cg + 5][la_row] = f2tf32(av1.y);
        As[la_cg + 6][la_row] = f2tf32(av1.z);
        As[la_cg + 7][la_row] = f2tf32(av1.w);
        Bs[lb_row][lb_c4 + 0]  = f2tf32(bv0.x);
        Bs[lb_row][lb_c4 + 1]  = f2tf32(bv0.y);
        Bs[lb_row][lb_c4 + 2]  = f2tf32(bv0.z);
        Bs[lb_row][lb_c4 + 3]  = f2tf32(bv0.w);
        Bs[lb_row][lb_c4 + 64] = f2tf32(bv1.x);
        Bs[lb_row][lb_c4 + 65] = f2tf32(bv1.y);
        Bs[lb_row][lb_c4 + 66] = f2tf32(bv1.z);
        Bs[lb_row][lb_c4 + 67] = f2tf32(bv1.w);
        __syncthreads();

        if (k0 + 16 < KDIM) {
            Ap += 16;
            Bp += (size_t)16 * N;
            av0 = *(const float4*)(Ap);
            av1 = *(const float4*)(Ap + 4);
            bv0 = *(const float4*)(Bp);
            bv1 = *(const float4*)(Bp + 64);
        }

#pragma unroll
        for (int ks = 0; ks < 16; ks += 8) {
            unsigned a[2][4], b[8][2];
#pragma unroll
            for (int mt = 0; mt < 2; mt++) {
                const int mb = wm + mt * 16;
                a[mt][0] = As[ks + tig    ][mb + gid    ];
                a[mt][1] = As[ks + tig    ][mb + gid + 8];
                a[mt][2] = As[ks + tig + 4][mb + gid    ];
                a[mt][3] = As[ks + tig + 4][mb + gid + 8];
            }
#pragma unroll
            for (int nt = 0; nt < 8; nt++) {
                const int nb = wn + nt * 8 + gid;
                b[nt][0] = Bs[ks + tig    ][nb];
                b[nt][1] = Bs[ks + tig + 4][nb];
            }
#pragma unroll
            for (int mt = 0; mt < 2; mt++)
#pragma unroll
                for (int nt = 0; nt < 8; nt++) {
                    asm volatile(
                        "mma.sync.aligned.m16n8k8.row.col.f32.tf32.tf32.f32 "
                        "{%0,%1,%2,%3}, {%4,%5,%6,%7}, {%8,%9}, {%0,%1,%2,%3};"
                        : "+f"(acc[mt][nt][0]), "+f"(acc[mt][nt][1]),
                          "+f"(acc[mt][nt][2]), "+f"(acc[mt][nt][3])
                        : "r"(a[mt][0]), "r"(a[mt][1]), "r"(a[mt][2]), "r"(a[mt][3]),
                          "r"(b[nt][0]), "r"(b[nt][1]));
                }
        }
        __syncthreads();
    }

#pragma unroll
    for (int mt = 0; mt < 2; mt++) {
#pragma unroll
        for (int rr = 0; rr < 2; rr++) {
            const int m = m0 + wm + mt * 16 + gid + rr * 8;
            const int bb  = m / LQ;
            const int pos = m - bb * LQ;
#pragma unroll
            for (int nt = 0; nt < 8; nt++) {
                const int n = n0 + wn + nt * 8 + tig * 2;
                float2 v;
                v.x = acc[mt][nt][rr * 2 + 0] + bias[n];
                v.y = acc[mt][nt][rr * 2 + 1] + bias[n + 1];
                if (mode == 0) {
                    *(float2*)&C[(size_t)m * N + n] = v;
                } else {
                    const int h = n >> 5;
                    const int c = n & 31;   // even
                    __half2 hv = __floats2half2_rn(v.x, v.y);
                    *(__half2*)&g_Vh[(((size_t)(bb * NH + h)) * LQ + pos) * DH + c] = hv;
                }
            }
        }
    }
}

// generic GEMM kernel (used for V and final output)
__global__ __launch_bounds__(256) void tf32gemm(
    const float* __restrict__ A, const float* __restrict__ B,
    const float* __restrict__ bias, float* __restrict__ C,
    int N, int mode)
{
    gemm_body(A, B, bias, C, N, blockIdx.y * 128, blockIdx.x * 128, mode);
}

// fused OFF + AW GEMM: grid.x = 3.  Blocks 0,1 -> query@Woff -> g_off (N=256);
// block 2 -> query@Wa -> g_aw (N=128).
__global__ __launch_bounds__(256) void tf32gemm_offaw(
    const float* __restrict__ A,
    const float* __restrict__ Woff, const float* __restrict__ boff,
    const float* __restrict__ Wa,   const float* __restrict__ ba)
{
    const int m0 = blockIdx.y * 128;
    if (blockIdx.x < 2) {
        gemm_body(A, Woff, boff, g_off, 256, m0, blockIdx.x * 128, 0);
    } else {
        gemm_body(A, Wa, ba, g_aw, 128, m0, 0, 0);
    }
}

// ---------------------------------------------------------------------------
// Double softmax (unchanged).
// ---------------------------------------------------------------------------
__global__ __launch_bounds__(256) void softmax2_kernel(float* __restrict__ buf)
{
    const int warp = threadIdx.x >> 5;
    const int lane = threadIdx.x & 31;
    const int row  = blockIdx.x * 8 + warp;
    float* p = buf + (size_t)row * 128 + lane * 4;

    float4 v = *(const float4*)p;

    float vm = fmaxf(fmaxf(v.x, v.y), fmaxf(v.z, v.w));
#pragma unroll
    for (int o = 16; o; o >>= 1) vm = fmaxf(vm, __shfl_xor_sync(~0u, vm, o));
    float e0 = expf(v.x - vm), e1 = expf(v.y - vm);
    float e2 = expf(v.z - vm), e3 = expf(v.w - vm);
    float s = e0 + e1 + e2 + e3;
#pragma unroll
    for (int o = 16; o; o >>= 1) s += __shfl_xor_sync(~0u, s, o);
    const float inv = 1.0f / s;
    const float t0 = e0 * inv, t1 = e1 * inv, t2 = e2 * inv, t3 = e3 * inv;

    float gm = fmaxf(fmaxf(t0, t1), fmaxf(t2, t3));
    gm = fmaxf(gm, __shfl_xor_sync(~0u, gm, 1));
    gm = fmaxf(gm, __shfl_xor_sync(~0u, gm, 2));
    float f0 = expf(t0 - gm), f1 = expf(t1 - gm);
    float f2 = expf(t2 - gm), f3 = expf(t3 - gm);
    float gs = f0 + f1 + f2 + f3;
    gs += __shfl_xor_sync(~0u, gs, 1);
    gs += __shfl_xor_sync(~0u, gs, 2);
    const float ginv = 1.0f / gs;

    float4 o4;
    o4.x = f0 * ginv; o4.y = f1 * ginv; o4.z = f2 * ginv; o4.w = f3 * ginv;
    *(float4*)p = o4;
}

// ---------------------------------------------------------------------------
// Sampling v4: occupancy-first.
// Warp h handles head h of query bq.  Lane = (unit u = lane>>2, quarter q).
// Pass i: unit u -> (point 2i+(u>>2), corner u&3); level l = i>>1 uniform.
// Phase A computes 8 combined weights + 8 *32-bit byte offsets* (not
// pointers).  Loads issued in 2 groups of 4 (hv = 16 regs, MLP=4).
// __launch_bounds__(256,3) caps regs at 85 -> 3 CTAs/SM (24 warps, 37.5%).
// ---------------------------------------------------------------------------
__global__ __launch_bounds__(256, 3) void msdeform_sample_kernel(
    const float* __restrict__ refpts)
{
    const int bq   = blockIdx.x;
    const int b    = bq / LQ;
    const int h    = threadIdx.x >> 5;
    const int lane = threadIdx.x & 31;
    const int u    = lane >> 2;       // unit 0..7
    const int q    = lane & 3;        // channel quarter

    const int starts[4] = {0, 4096, 5120, 5376};
    const int sizes [4] = {64, 32, 16, 8};

    const float2* offp2 = (const float2*)(g_off + (size_t)bq * 256 + h * 32);
    const float*  awp   = g_aw + (size_t)bq * 128 + h * 16;
    const float*  refp  = refpts + (size_t)bq * 8;
    const char*   vbase = (const char*)(g_Vh + ((size_t)(b * NH + h)) * LQ * DH);

    const int cidx = u & 3;
    const int psel = u >> 2;

    // reference points for the 4 levels, loaded once
    const float4 ra = __ldg((const float4*)refp);
    const float4 rb = __ldg((const float4*)(refp + 4));
    const float rxv[4] = {ra.x, ra.z, rb.x, rb.z};
    const float ryv[4] = {ra.y, ra.w, rb.y, rb.w};

    // Phase A: 8 combined weights + 8 byte offsets (32-bit)
    unsigned offs[8];
    float cwv[8];
#pragma unroll
    for (int i = 0; i < 8; i++) {
        const int l     = i >> 1;
        const int S     = sizes[l];
        const int start = starts[l];
        const float inv_fs = 1.0f / (float)S;   // exact (power of 2)

        const int pidx = i * 2 + psel;

        const float2 o = __ldg(&offp2[pidx]);
        const float  w = __ldg(&awp[pidx]);

        const float cx = rxv[l] + o.x * inv_fs;
        const float cy = ryv[l] + o.y * inv_fs;
        const float x = 0.5f * ((cx + 1.0f) * (float)(S - 2));
        const float y = 0.5f * ((cy + 1.0f) * (float)(S - 2));

        const int x0 = (int)floorf(x);
        const int y0 = (int)floorf(y);
        const int x0c = min(max(x0, 0),     S - 1);
        const int x1c = min(max(x0 + 1, 0), S - 1);
        const int y0c = min(max(y0, 0),     S - 1);
        const int y1c = min(max(y0 + 1, 0), S - 1);
        const float x0f = (float)x0c, x1f = (float)x1c;
        const float y0f = (float)y0c, y1f = (float)y1c;

        const int   xi = (cidx & 2) ? x1c : x0c;
        const int   yi = (cidx & 1) ? y1c : y0c;
        const float wx = (cidx & 2) ? (x - x0f) : (x1f - x);
        const float wy = (cidx & 1) ? (y - y0f) : (y1f - y);

        cwv[i]  = w * wx * wy;
        // byte offset: row * DH halves * 2 B + q*8 halves * 2 B
        offs[i] = (unsigned)((start + yi * S + xi) * (DH * 2) + q * 16);
    }

    // Phases B+C in two groups of 4 (hv = 16 regs, MLP = 4)
    float acc[8];
#pragma unroll
    for (int j = 0; j < 8; j++) acc[j] = 0.0f;

#pragma unroll
    for (int g = 0; g < 2; g++) {
        uint4 hv[4];
#pragma unroll
        for (int j = 0; j < 4; j++)
            hv[j] = __ldg((const uint4*)(vbase + offs[g * 4 + j]));
#pragma unroll
        for (int j = 0; j < 4; j++) {
            const float cw = cwv[g * 4 + j];
            const float2 f0 = __half22float2(*(const __half2*)&hv[j].x);
            const float2 f1 = __half22float2(*(const __half2*)&hv[j].y);
            const float2 f2 = __half22float2(*(const __half2*)&hv[j].z);
            const float2 f3 = __half22float2(*(const __half2*)&hv[j].w);
            acc[0] = fmaf(cw, f0.x, acc[0]);
            acc[1] = fmaf(cw, f0.y, acc[1]);
            acc[2] = fmaf(cw, f1.x, acc[2]);
            acc[3] = fmaf(cw, f1.y, acc[3]);
            acc[4] = fmaf(cw, f2.x, acc[4]);
            acc[5] = fmaf(cw, f2.y, acc[5]);
            acc[6] = fmaf(cw, f3.x, acc[6]);
            acc[7] = fmaf(cw, f3.y, acc[7]);
        }
    }

    // reduce across the 8 units (lanes q, q+4, ..., q+28)
#pragma unroll
    for (int m = 4; m <= 16; m <<= 1)
#pragma unroll
        for (int j = 0; j < 8; j++)
            acc[j] += __shfl_xor_sync(~0u, acc[j], m);

    if (u == 0) {
        float* dst = g_mid + (size_t)bq * 256 + h * 32 + q * 8;
        *(float4*)(dst + 0) = make_float4(acc[0], acc[1], acc[2], acc[3]);
        *(float4*)(dst + 4) = make_float4(acc[4], acc[5], acc[6], acc[7]);
    }
}

// ---------------------------------------------------------------------------
// launch
// ---------------------------------------------------------------------------
extern "C" void kernel_launch(void* const* d_in, const int* in_sizes, int n_in,
                              void* d_out, int out_size)
{
    const float* query = (const float*)d_in[0];
    const float* value = (const float*)d_in[1];
    const float* refp  = (const float*)d_in[2];
    const float* Wv    = (const float*)d_in[3];
    const float* bv    = (const float*)d_in[4];
    const float* Woff  = (const float*)d_in[5];
    const float* boff  = (const float*)d_in[6];
    const float* Wa    = (const float*)d_in[7];
    const float* ba    = (const float*)d_in[8];
    const float* Wout  = (const float*)d_in[9];
    const float* bout  = (const float*)d_in[10];
    float* out = (float*)d_out;

    float *pAw, *pMid;
    cudaGetSymbolAddress((void**)&pAw,  g_aw);
    cudaGetSymbolAddress((void**)&pMid, g_mid);

    const dim3 gN256(2, MROWS / 128);   // (2, 340)
    const dim3 gOffAw(3, MROWS / 128);  // (3, 340)

    tf32gemm<<<gN256, 256>>>(value, Wv, bv, /*unused in mode1*/ pMid, 256, 1);
    tf32gemm_offaw<<<gOffAw, 256>>>(query, Woff, boff, Wa, ba);
    softmax2_kernel<<<MROWS / 8, 256>>>(pAw);
    msdeform_sample_kernel<<<MROWS, 256>>>(refp);
    tf32gemm<<<gN256, 256>>>(pMid, Wout, bout, out, 256, 0);
}

// round 10
// speedup vs baseline: 1.1918x; 1.0572x over previous
#include <cuda_runtime.h>
#include <cuda_fp16.h>

// ---------------------------------------------------------------------------
// MSDeformAttention  (bs=8, Lq=Lv=5440, D=256, 8 heads x 32, 4 levels x 4 pts)
//
//   1) V      = value @ Wv + bv        (tf32 MMA, pipelined, -> fp16 g_Vh)
//   2) OFF/AW = query @ [Woff|Wa]      (single fused tf32 MMA launch)
//   3) AW     = softmax16(softmax128(AWL))
//   4) MID    = bilinear-gather v5 (two half-passes, 64-reg, occ 4 CTA/SM)
//   5) out    = MID @ Wout + bout      (tf32 MMA, pipelined)
// ---------------------------------------------------------------------------

#define LQ     5440
#define BSZ    8
#define NH     8
#define DH     32
#define DMODEL 256
#define MROWS  (BSZ * LQ)          // 43520
#define KDIM   256

// scratch (static device globals: allocation-free)
__device__ __half g_Vh [BSZ * NH * LQ * DH];    // [b][h][pos][c]  fp16
__device__ float  g_off[(size_t)MROWS * DMODEL];
__device__ float  g_aw [(size_t)MROWS * 128];
__device__ float  g_mid[(size_t)MROWS * DMODEL];

// tf32 round (rna); returns the b32 bit pattern (cvt.rna.tf32 needs .b32 dst).
__device__ __forceinline__ unsigned f2tf32(float x) {
    unsigned y;
    asm("cvt.rna.tf32.f32 %0, %1;" : "=r"(y) : "f"(x));
    return y;
}

// ---------------------------------------------------------------------------
// Shared GEMM body (unchanged): C[M,N] = A[M,256] @ B[256,N] + bias[N]
// Block tile 128x128, BK=16, 256 threads = 8 warps (4m x 2n), warp tile 32x64.
// Software-pipelined (register prefetch of next k-tile).
// mode 0: row-major fp32 C.   mode 1: permuted fp16 write into g_Vh.
// ---------------------------------------------------------------------------
__device__ __forceinline__ void gemm_body(
    const float* __restrict__ A, const float* __restrict__ B,
    const float* __restrict__ bias, float* __restrict__ C,
    int N, int m0, int n0, int mode)
{
    __shared__ unsigned As[16][136];   // [k][m]  (tf32 bit patterns)
    __shared__ unsigned Bs[16][136];   // [k][n]

    const int tid  = threadIdx.x;
    const int lane = tid & 31;
    const int warp = tid >> 5;
    const int gid  = lane >> 2;     // 0..7
    const int tig  = lane & 3;      // 0..3
    const int wm   = (warp >> 1) * 32;
    const int wn   = (warp & 1) * 64;

    const int la_row = tid >> 1;
    const int la_cg  = (tid & 1) * 8;
    const int lb_row = tid >> 4;
    const int lb_c4  = (tid & 15) * 4;

    const float* Ap = A + (size_t)(m0 + la_row) * KDIM + la_cg;
    const float* Bp = B + (size_t)lb_row * N + n0 + lb_c4;

    float acc[2][8][4];
#pragma unroll
    for (int mt = 0; mt < 2; mt++)
#pragma unroll
        for (int nt = 0; nt < 8; nt++)
#pragma unroll
            for (int r = 0; r < 4; r++) acc[mt][nt][r] = 0.0f;

    float4 av0 = *(const float4*)(Ap);
    float4 av1 = *(const float4*)(Ap + 4);
    float4 bv0 = *(const float4*)(Bp);
    float4 bv1 = *(const float4*)(Bp + 64);

    for (int k0 = 0; k0 < KDIM; k0 += 16) {
        As[la_cg + 0][la_row] = f2tf32(av0.x);
        As[la_cg + 1][la_row] = f2tf32(av0.y);
        As[la_cg + 2][la_row] = f2tf32(av0.z);
        As[la_cg + 3][la_row] = f2tf32(av0.w);
        As[la_cg + 4][la_row] = f2tf32(av1.x);
        As[la_cg + 5][la_row] = f2tf32(av1.y);
        As[la_cg + 6][la_row] = f2tf32(av1.z);
        As[la_cg + 7][la_row] = f2tf32(av1.w);
        Bs[lb_row][lb_c4 + 0]  = f2tf32(bv0.x);
        Bs[lb_row][lb_c4 + 1]  = f2tf32(bv0.y);
        Bs[lb_row][lb_c4 + 2]  = f2tf32(bv0.z);
        Bs[lb_row][lb_c4 + 3]  = f2tf32(bv0.w);
        Bs[lb_row][lb_c4 + 64] = f2tf32(bv1.x);
        Bs[lb_row][lb_c4 + 65] = f2tf32(bv1.y);
        Bs[lb_row][lb_c4 + 66] = f2tf32(bv1.z);
        Bs[lb_row][lb_c4 + 67] = f2tf32(bv1.w);
        __syncthreads();

        if (k0 + 16 < KDIM) {
            Ap += 16;
            Bp += (size_t)16 * N;
            av0 = *(const float4*)(Ap);
            av1 = *(const float4*)(Ap + 4);
            bv0 = *(const float4*)(Bp);
            bv1 = *(const float4*)(Bp + 64);
        }

#pragma unroll
        for (int ks = 0; ks < 16; ks += 8) {
            unsigned a[2][4], b[8][2];
#pragma unroll
            for (int mt = 0; mt < 2; mt++) {
                const int mb = wm + mt * 16;
                a[mt][0] = As[ks + tig    ][mb + gid    ];
                a[mt][1] = As[ks + tig    ][mb + gid + 8];
                a[mt][2] = As[ks + tig + 4][mb + gid    ];
                a[mt][3] = As[ks + tig + 4][mb + gid + 8];
            }
#pragma unroll
            for (int nt = 0; nt < 8; nt++) {
                const int nb = wn + nt * 8 + gid;
                b[nt][0] = Bs[ks + tig    ][nb];
                b[nt][1] = Bs[ks + tig + 4][nb];
            }
#pragma unroll
            for (int mt = 0; mt < 2; mt++)
#pragma unroll
                for (int nt = 0; nt < 8; nt++) {
                    asm volatile(
                        "mma.sync.aligned.m16n8k8.row.col.f32.tf32.tf32.f32 "
                        "{%0,%1,%2,%3}, {%4,%5,%6,%7}, {%8,%9}, {%0,%1,%2,%3};"
                        : "+f"(acc[mt][nt][0]), "+f"(acc[mt][nt][1]),
                          "+f"(acc[mt][nt][2]), "+f"(acc[mt][nt][3])
                        : "r"(a[mt][0]), "r"(a[mt][1]), "r"(a[mt][2]), "r"(a[mt][3]),
                          "r"(b[nt][0]), "r"(b[nt][1]));
                }
        }
        __syncthreads();
    }

#pragma unroll
    for (int mt = 0; mt < 2; mt++) {
#pragma unroll
        for (int rr = 0; rr < 2; rr++) {
            const int m = m0 + wm + mt * 16 + gid + rr * 8;
            const int bb  = m / LQ;
            const int pos = m - bb * LQ;
#pragma unroll
            for (int nt = 0; nt < 8; nt++) {
                const int n = n0 + wn + nt * 8 + tig * 2;
                float2 v;
                v.x = acc[mt][nt][rr * 2 + 0] + bias[n];
                v.y = acc[mt][nt][rr * 2 + 1] + bias[n + 1];
                if (mode == 0) {
                    *(float2*)&C[(size_t)m * N + n] = v;
                } else {
                    const int h = n >> 5;
                    const int c = n & 31;   // even
                    __half2 hv = __floats2half2_rn(v.x, v.y);
                    *(__half2*)&g_Vh[(((size_t)(bb * NH + h)) * LQ + pos) * DH + c] = hv;
                }
            }
        }
    }
}

// generic GEMM kernel (used for V and final output)
__global__ __launch_bounds__(256) void tf32gemm(
    const float* __restrict__ A, const float* __restrict__ B,
    const float* __restrict__ bias, float* __restrict__ C,
    int N, int mode)
{
    gemm_body(A, B, bias, C, N, blockIdx.y * 128, blockIdx.x * 128, mode);
}

// fused OFF + AW GEMM: grid.x = 3.  Blocks 0,1 -> query@Woff -> g_off (N=256);
// block 2 -> query@Wa -> g_aw (N=128).
__global__ __launch_bounds__(256) void tf32gemm_offaw(
    const float* __restrict__ A,
    const float* __restrict__ Woff, const float* __restrict__ boff,
    const float* __restrict__ Wa,   const float* __restrict__ ba)
{
    const int m0 = blockIdx.y * 128;
    if (blockIdx.x < 2) {
        gemm_body(A, Woff, boff, g_off, 256, m0, blockIdx.x * 128, 0);
    } else {
        gemm_body(A, Wa, ba, g_aw, 128, m0, 0, 0);
    }
}

// ---------------------------------------------------------------------------
// Double softmax (unchanged).
// ---------------------------------------------------------------------------
__global__ __launch_bounds__(256) void softmax2_kernel(float* __restrict__ buf)
{
    const int warp = threadIdx.x >> 5;
    const int lane = threadIdx.x & 31;
    const int row  = blockIdx.x * 8 + warp;
    float* p = buf + (size_t)row * 128 + lane * 4;

    float4 v = *(const float4*)p;

    float vm = fmaxf(fmaxf(v.x, v.y), fmaxf(v.z, v.w));
#pragma unroll
    for (int o = 16; o; o >>= 1) vm = fmaxf(vm, __shfl_xor_sync(~0u, vm, o));
    float e0 = expf(v.x - vm), e1 = expf(v.y - vm);
    float e2 = expf(v.z - vm), e3 = expf(v.w - vm);
    float s = e0 + e1 + e2 + e3;
#pragma unroll
    for (int o = 16; o; o >>= 1) s += __shfl_xor_sync(~0u, s, o);
    const float inv = 1.0f / s;
    const float t0 = e0 * inv, t1 = e1 * inv, t2 = e2 * inv, t3 = e3 * inv;

    float gm = fmaxf(fmaxf(t0, t1), fmaxf(t2, t3));
    gm = fmaxf(gm, __shfl_xor_sync(~0u, gm, 1));
    gm = fmaxf(gm, __shfl_xor_sync(~0u, gm, 2));
    float f0 = expf(t0 - gm), f1 = expf(t1 - gm);
    float f2 = expf(t2 - gm), f3 = expf(t3 - gm);
    float gs = f0 + f1 + f2 + f3;
    gs += __shfl_xor_sync(~0u, gs, 1);
    gs += __shfl_xor_sync(~0u, gs, 2);
    const float ginv = 1.0f / gs;

    float4 o4;
    o4.x = f0 * ginv; o4.y = f1 * ginv; o4.z = f2 * ginv; o4.w = f3 * ginv;
    *(float4*)p = o4;
}

// ---------------------------------------------------------------------------
// Sampling v5: two half-passes for 64-reg footprint -> 4 CTAs/SM (50% occ).
// Warp h handles head h of query bq.  Lane = (unit u = lane>>2, quarter q).
// Half g handles levels 2g, 2g+1 (points 8g..8g+7): per half compute 4
// (offset, cw) pairs, issue 4 LDG.128, accumulate.  Tail: shfl reduce
// (4,8,16), lanes 0-3 (u==0) write 32 floats.
// ---------------------------------------------------------------------------
__global__ __launch_bounds__(256, 4) void msdeform_sample_kernel(
    const float* __restrict__ refpts)
{
    const int bq   = blockIdx.x;
    const int b    = bq / LQ;
    const int h    = threadIdx.x >> 5;
    const int lane = threadIdx.x & 31;
    const int u    = lane >> 2;       // unit 0..7
    const int q    = lane & 3;        // channel quarter

    const int starts[4] = {0, 4096, 5120, 5376};
    const int sizes [4] = {64, 32, 16, 8};

    const float2* offp2 = (const float2*)(g_off + (size_t)bq * 256 + h * 32);
    const float*  awp   = g_aw + (size_t)bq * 128 + h * 16;
    const float*  refp  = refpts + (size_t)bq * 8;
    const char*   vbase = (const char*)(g_Vh + ((size_t)(b * NH + h)) * LQ * DH);

    const int cidx = u & 3;
    const int psel = u >> 2;

    float acc[8];
#pragma unroll
    for (int j = 0; j < 8; j++) acc[j] = 0.0f;

#pragma unroll
    for (int g = 0; g < 2; g++) {
        // ref points for this half's two levels (2g, 2g+1)
        const float4 r4 = __ldg((const float4*)(refp + g * 4));
        const float rxv[2] = {r4.x, r4.z};
        const float ryv[2] = {r4.y, r4.w};

        unsigned offs[4];
        float    cwv[4];
#pragma unroll
        for (int j = 0; j < 4; j++) {
            const int i     = g * 4 + j;
            const int l     = i >> 1;            // global level
            const int ll    = j >> 1;            // level within half
            const int S     = sizes[l];
            const int start = starts[l];
            const float inv_fs = 1.0f / (float)S;   // exact (power of 2)

            const int pidx = i * 2 + psel;

            const float2 o = __ldg(&offp2[pidx]);
            const float  w = __ldg(&awp[pidx]);

            const float cx = rxv[ll] + o.x * inv_fs;
            const float cy = ryv[ll] + o.y * inv_fs;
            const float x = 0.5f * ((cx + 1.0f) * (float)(S - 2));
            const float y = 0.5f * ((cy + 1.0f) * (float)(S - 2));

            const int x0 = (int)floorf(x);
            const int y0 = (int)floorf(y);
            const int x0c = min(max(x0, 0),     S - 1);
            const int x1c = min(max(x0 + 1, 0), S - 1);
            const int y0c = min(max(y0, 0),     S - 1);
            const int y1c = min(max(y0 + 1, 0), S - 1);
            const float x0f = (float)x0c, x1f = (float)x1c;
            const float y0f = (float)y0c, y1f = (float)y1c;

            const int   xi = (cidx & 2) ? x1c : x0c;
            const int   yi = (cidx & 1) ? y1c : y0c;
            const float wx = (cidx & 2) ? (x - x0f) : (x1f - x);
            const float wy = (cidx & 1) ? (y - y0f) : (y1f - y);

            cwv[j]  = w * wx * wy;
            offs[j] = (unsigned)((start + yi * S + xi) * (DH * 2) + q * 16);
        }

        uint4 hv[4];
#pragma unroll
        for (int j = 0; j < 4; j++)
            hv[j] = __ldg((const uint4*)(vbase + offs[j]));

#pragma unroll
        for (int j = 0; j < 4; j++) {
            const float cw = cwv[j];
            const float2 f0 = __half22float2(*(const __half2*)&hv[j].x);
            const float2 f1 = __half22float2(*(const __half2*)&hv[j].y);
            const float2 f2 = __half22float2(*(const __half2*)&hv[j].z);
            const float2 f3 = __half22float2(*(const __half2*)&hv[j].w);
            acc[0] = fmaf(cw, f0.x, acc[0]);
            acc[1] = fmaf(cw, f0.y, acc[1]);
            acc[2] = fmaf(cw, f1.x, acc[2]);
            acc[3] = fmaf(cw, f1.y, acc[3]);
            acc[4] = fmaf(cw, f2.x, acc[4]);
            acc[5] = fmaf(cw, f2.y, acc[5]);
            acc[6] = fmaf(cw, f3.x, acc[6]);
            acc[7] = fmaf(cw, f3.y, acc[7]);
        }
    }

    // reduce across the 8 units (lanes q, q+4, ..., q+28)
#pragma unroll
    for (int m = 4; m <= 16; m <<= 1)
#pragma unroll
        for (int j = 0; j < 8; j++)
            acc[j] += __shfl_xor_sync(~0u, acc[j], m);

    if (u == 0) {
        float* dst = g_mid + (size_t)bq * 256 + h * 32 + q * 8;
        *(float4*)(dst + 0) = make_float4(acc[0], acc[1], acc[2], acc[3]);
        *(float4*)(dst + 4) = make_float4(acc[4], acc[5], acc[6], acc[7]);
    }
}

// ---------------------------------------------------------------------------
// launch
// ---------------------------------------------------------------------------
extern "C" void kernel_launch(void* const* d_in, const int* in_sizes, int n_in,
                              void* d_out, int out_size)
{
    const float* query = (const float*)d_in[0];
    const float* value = (const float*)d_in[1];
    const float* refp  = (const float*)d_in[2];
    const float* Wv    = (const float*)d_in[3];
    const float* bv    = (const float*)d_in[4];
    const float* Woff  = (const float*)d_in[5];
    const float* boff  = (const float*)d_in[6];
    const float* Wa    = (const float*)d_in[7];
    const float* ba    = (const float*)d_in[8];
    const float* Wout  = (const float*)d_in[9];
    const float* bout  = (const float*)d_in[10];
    float* out = (float*)d_out;

    float *pAw, *pMid;
    cudaGetSymbolAddress((void**)&pAw,  g_aw);
    cudaGetSymbolAddress((void**)&pMid, g_mid);

    const dim3 gN256(2, MROWS / 128);   // (2, 340)
    const dim3 gOffAw(3, MROWS / 128);  // (3, 340)

    tf32gemm<<<gN256, 256>>>(value, Wv, bv, /*unused in mode1*/ pMid, 256, 1);
    tf32gemm_offaw<<<gOffAw, 256>>>(query, Woff, boff, Wa, ba);
    softmax2_kernel<<<MROWS / 8, 256>>>(pAw);
    msdeform_sample_kernel<<<MROWS, 256>>>(refp);
    tf32gemm<<<gN256, 256>>>(pMid, Wout, bout, out, 256, 0);
}

// round 11
// speedup vs baseline: 1.2574x; 1.0551x over previous
#include <cuda_runtime.h>
#include <cuda_fp16.h>

// ---------------------------------------------------------------------------
// MSDeformAttention  (bs=8, Lq=Lv=5440, D=256, 8 heads x 32, 4 levels x 4 pts)
//
//   1) V      = value @ Wv + bv        (tf32 MMA, pipelined, -> fp16 g_Vh)
//   2) OFF/AW = query @ [Woff|Wa]      (single fused tf32 MMA launch)
//   3) AW     = softmax16(softmax128(AWL))
//   4) MID    = bilinear-gather v6 (shuffle-distributed point math)
//   5) out    = MID @ Wout + bout      (tf32 MMA, pipelined)
// ---------------------------------------------------------------------------

#define LQ     5440
#define BSZ    8
#define NH     8
#define DH     32
#define DMODEL 256
#define MROWS  (BSZ * LQ)          // 43520
#define KDIM   256

// scratch (static device globals: allocation-free)
__device__ __half g_Vh [BSZ * NH * LQ * DH];    // [b][h][pos][c]  fp16
__device__ float  g_off[(size_t)MROWS * DMODEL];
__device__ float  g_aw [(size_t)MROWS * 128];
__device__ float  g_mid[(size_t)MROWS * DMODEL];

// tf32 round (rna); returns the b32 bit pattern (cvt.rna.tf32 needs .b32 dst).
__device__ __forceinline__ unsigned f2tf32(float x) {
    unsigned y;
    asm("cvt.rna.tf32.f32 %0, %1;" : "=r"(y) : "f"(x));
    return y;
}

// ---------------------------------------------------------------------------
// Shared GEMM body (unchanged): C[M,N] = A[M,256] @ B[256,N] + bias[N]
// Block tile 128x128, BK=16, 256 threads = 8 warps (4m x 2n), warp tile 32x64.
// Software-pipelined (register prefetch of next k-tile).
// mode 0: row-major fp32 C.   mode 1: permuted fp16 write into g_Vh.
// ---------------------------------------------------------------------------
__device__ __forceinline__ void gemm_body(
    const float* __restrict__ A, const float* __restrict__ B,
    const float* __restrict__ bias, float* __restrict__ C,
    int N, int m0, int n0, int mode)
{
    __shared__ unsigned As[16][136];   // [k][m]  (tf32 bit patterns)
    __shared__ unsigned Bs[16][136];   // [k][n]

    const int tid  = threadIdx.x;
    const int lane = tid & 31;
    const int warp = tid >> 5;
    const int gid  = lane >> 2;     // 0..7
    const int tig  = lane & 3;      // 0..3
    const int wm   = (warp >> 1) * 32;
    const int wn   = (warp & 1) * 64;

    const int la_row = tid >> 1;
    const int la_cg  = (tid & 1) * 8;
    const int lb_row = tid >> 4;
    const int lb_c4  = (tid & 15) * 4;

    const float* Ap = A + (size_t)(m0 + la_row) * KDIM + la_cg;
    const float* Bp = B + (size_t)lb_row * N + n0 + lb_c4;

    float acc[2][8][4];
#pragma unroll
    for (int mt = 0; mt < 2; mt++)
#pragma unroll
        for (int nt = 0; nt < 8; nt++)
#pragma unroll
            for (int r = 0; r < 4; r++) acc[mt][nt][r] = 0.0f;

    float4 av0 = *(const float4*)(Ap);
    float4 av1 = *(const float4*)(Ap + 4);
    float4 bv0 = *(const float4*)(Bp);
    float4 bv1 = *(const float4*)(Bp + 64);

    for (int k0 = 0; k0 < KDIM; k0 += 16) {
        As[la_cg + 0][la_row] = f2tf32(av0.x);
        As[la_cg + 1][la_row] = f2tf32(av0.y);
        As[la_cg + 2][la_row] = f2tf32(av0.z);
        As[la_cg + 3][la_row] = f2tf32(av0.w);
        As[la_cg + 4][la_row] = f2tf32(av1.x);
        As[la_cg + 5][la_row] = f2tf32(av1.y);
        As[la_cg + 6][la_row] = f2tf32(av1.z);
        As[la_cg + 7][la_row] = f2tf32(av1.w);
        Bs[lb_row][lb_c4 + 0]  = f2tf32(bv0.x);
        Bs[lb_row][lb_c4 + 1]  = f2tf32(bv0.y);
        Bs[lb_row][lb_c4 + 2]  = f2tf32(bv0.z);
        Bs[lb_row][lb_c4 + 3]  = f2tf32(bv0.w);
        Bs[lb_row][lb_c4 + 64] = f2tf32(bv1.x);
        Bs[lb_row][lb_c4 + 65] = f2tf32(bv1.y);
        Bs[lb_row][lb_c4 + 66] = f2tf32(bv1.z);
        Bs[lb_row][lb_c4 + 67] = f2tf32(bv1.w);
        __syncthreads();

        if (k0 + 16 < KDIM) {
            Ap += 16;
            Bp += (size_t)16 * N;
            av0 = *(const float4*)(Ap);
            av1 = *(const float4*)(Ap + 4);
            bv0 = *(const float4*)(Bp);
            bv1 = *(const float4*)(Bp + 64);
        }

#pragma unroll
        for (int ks = 0; ks < 16; ks += 8) {
            unsigned a[2][4], b[8][2];
#pragma unroll
            for (int mt = 0; mt < 2; mt++) {
                const int mb = wm + mt * 16;
                a[mt][0] = As[ks + tig    ][mb + gid    ];
                a[mt][1] = As[ks + tig    ][mb + gid + 8];
                a[mt][2] = As[ks + tig + 4][mb + gid    ];
                a[mt][3] = As[ks + tig + 4][mb + gid + 8];
            }
#pragma unroll
            for (int nt = 0; nt < 8; nt++) {
                const int nb = wn + nt * 8 + gid;
                b[nt][0] = Bs[ks + tig    ][nb];
                b[nt][1] = Bs[ks + tig + 4][nb];
            }
#pragma unroll
            for (int mt = 0; mt < 2; mt++)
#pragma unroll
                for (int nt = 0; nt < 8; nt++) {
                    asm volatile(
                        "mma.sync.aligned.m16n8k8.row.col.f32.tf32.tf32.f32 "
                        "{%0,%1,%2,%3}, {%4,%5,%6,%7}, {%8,%9}, {%0,%1,%2,%3};"
                        : "+f"(acc[mt][nt][0]), "+f"(acc[mt][nt][1]),
                          "+f"(acc[mt][nt][2]), "+f"(acc[mt][nt][3])
                        : "r"(a[mt][0]), "r"(a[mt][1]), "r"(a[mt][2]), "r"(a[mt][3]),
                          "r"(b[nt][0]), "r"(b[nt][1]));
                }
        }
        __syncthreads();
    }

#pragma unroll
    for (int mt = 0; mt < 2; mt++) {
#pragma unroll
        for (int rr = 0; rr < 2; rr++) {
            const int m = m0 + wm + mt * 16 + gid + rr * 8;
            const int bb  = m / LQ;
            const int pos = m - bb * LQ;
#pragma unroll
            for (int nt = 0; nt < 8; nt++) {
                const int n = n0 + wn + nt * 8 + tig * 2;
                float2 v;
                v.x = acc[mt][nt][rr * 2 + 0] + bias[n];
                v.y = acc[mt][nt][rr * 2 + 1] + bias[n + 1];
                if (mode == 0) {
                    *(float2*)&C[(size_t)m * N + n] = v;
                } else {
                    const int h = n >> 5;
                    const int c = n & 31;   // even
                    __half2 hv = __floats2half2_rn(v.x, v.y);
                    *(__half2*)&g_Vh[(((size_t)(bb * NH + h)) * LQ + pos) * DH + c] = hv;
                }
            }
        }
    }
}

// generic GEMM kernel (used for V and final output)
__global__ __launch_bounds__(256) void tf32gemm(
    const float* __restrict__ A, const float* __restrict__ B,
    const float* __restrict__ bias, float* __restrict__ C,
    int N, int mode)
{
    gemm_body(A, B, bias, C, N, blockIdx.y * 128, blockIdx.x * 128, mode);
}

// fused OFF + AW GEMM: grid.x = 3.  Blocks 0,1 -> query@Woff -> g_off (N=256);
// block 2 -> query@Wa -> g_aw (N=128).
__global__ __launch_bounds__(256) void tf32gemm_offaw(
    const float* __restrict__ A,
    const float* __restrict__ Woff, const float* __restrict__ boff,
    const float* __restrict__ Wa,   const float* __restrict__ ba)
{
    const int m0 = blockIdx.y * 128;
    if (blockIdx.x < 2) {
        gemm_body(A, Woff, boff, g_off, 256, m0, blockIdx.x * 128, 0);
    } else {
        gemm_body(A, Wa, ba, g_aw, 128, m0, 0, 0);
    }
}

// ---------------------------------------------------------------------------
// Double softmax (unchanged).
// ---------------------------------------------------------------------------
__global__ __launch_bounds__(256) void softmax2_kernel(float* __restrict__ buf)
{
    const int warp = threadIdx.x >> 5;
    const int lane = threadIdx.x & 31;
    const int row  = blockIdx.x * 8 + warp;
    float* p = buf + (size_t)row * 128 + lane * 4;

    float4 v = *(const float4*)p;

    float vm = fmaxf(fmaxf(v.x, v.y), fmaxf(v.z, v.w));
#pragma unroll
    for (int o = 16; o; o >>= 1) vm = fmaxf(vm, __shfl_xor_sync(~0u, vm, o));
    float e0 = expf(v.x - vm), e1 = expf(v.y - vm);
    float e2 = expf(v.z - vm), e3 = expf(v.w - vm);
    float s = e0 + e1 + e2 + e3;
#pragma unroll
    for (int o = 16; o; o >>= 1) s += __shfl_xor_sync(~0u, s, o);
    const float inv = 1.0f / s;
    const float t0 = e0 * inv, t1 = e1 * inv, t2 = e2 * inv, t3 = e3 * inv;

    float gm = fmaxf(fmaxf(t0, t1), fmaxf(t2, t3));
    gm = fmaxf(gm, __shfl_xor_sync(~0u, gm, 1));
    gm = fmaxf(gm, __shfl_xor_sync(~0u, gm, 2));
    float f0 = expf(t0 - gm), f1 = expf(t1 - gm);
    float f2 = expf(t2 - gm), f3 = expf(t3 - gm);
    float gs = f0 + f1 + f2 + f3;
    gs += __shfl_xor_sync(~0u, gs, 1);
    gs += __shfl_xor_sync(~0u, gs, 2);
    const float ginv = 1.0f / gs;

    float4 o4;
    o4.x = f0 * ginv; o4.y = f1 * ginv; o4.z = f2 * ginv; o4.w = f3 * ginv;
    *(float4*)p = o4;
}

// ---------------------------------------------------------------------------
// Sampling v6: shuffle-distributed point math.
//
// Warp h handles head h of query bq.  Consumers: lane = (unit u = lane>>2,
// quarter q = lane&3); pass i needs pair (pidx = 2i + (lane>>4),
// cidx = u&3) with cidx bit1 = x side, bit0 = y side.
//
// Producers (Phase A): lane l computes point pidx = l>>1 ONCE and emits its
// two corners with x side = l&1:  slot0 = y0 corner, slot1 = y1 corner
// (offs0/offs1 = byte row offsets, cw0/cw1 = combined weights).
//
// Phase B pass i: owner = ((2i + (lane>>4))<<1) | (cidx>>1); slot = cidx&1
// (lane-constant).  4 shfl + 2 sel + 1 add per pass, then LDG.128.
// ---------------------------------------------------------------------------
__global__ __launch_bounds__(256, 4) void msdeform_sample_kernel(
    const float* __restrict__ refpts)
{
    const int bq   = blockIdx.x;
    const int b    = bq / LQ;
    const int h    = threadIdx.x >> 5;
    const int lane = threadIdx.x & 31;
    const int q    = lane & 3;        // channel quarter (consumer)

    const float2* offp2 = (const float2*)(g_off + (size_t)bq * 256 + h * 32);
    const float*  awp   = g_aw + (size_t)bq * 128 + h * 16;
    const float*  refp  = refpts + (size_t)bq * 8;
    const char*   vbase = (const char*)(g_Vh + ((size_t)(b * NH + h)) * LQ * DH);

    // ---- Phase A (producer): this lane's point = lane>>1, x side = lane&1 ----
    unsigned offs0, offs1;
    float cw0, cw1;
    {
        const int own_p = lane >> 1;          // point 0..15
        const int xside = lane & 1;           // corner x side
        const int l     = own_p >> 2;         // level 0..3
        const int S     = 64 >> l;
        const int start = (16384 - ((S * S) << 2)) / 3;   // 0,4096,5120,5376
        const float inv_S = __int_as_float((121 + l) << 23);  // exact 1/S
        const float c1  = 0.5f * (float)S - 1.0f;             // 0.5*(S-2)
        const float a   = c1 * inv_S;                         // exact

        const float2 r = __ldg((const float2*)(refp + l * 2));
        const float2 o = __ldg(&offp2[own_p]);
        const float  w = __ldg(&awp[own_p]);

        const float x = fmaf(o.x, a, fmaf(r.x, c1, c1));
        const float y = fmaf(o.y, a, fmaf(r.y, c1, c1));

        const int x0 = (int)floorf(x);
        const int y0 = (int)floorf(y);
        const int x0c = min(max(x0, 0),     S - 1);
        const int x1c = min(max(x0 + 1, 0), S - 1);
        const int y0c = min(max(y0, 0),     S - 1);
        const int y1c = min(max(y0 + 1, 0), S - 1);
        const float x0f = (float)x0c, x1f = (float)x1c;
        const float y0f = (float)y0c, y1f = (float)y1c;

        const int   xi  = xside ? x1c : x0c;
        const float wxv = xside ? (x - x0f) : (x1f - x);
        const float wwx = w * wxv;

        const int colb = start + xi;
        offs0 = (unsigned)((colb + y0c * S) * (DH * 2));
        offs1 = (unsigned)((colb + y1c * S) * (DH * 2));
        cw0 = wwx * (y1f - y);
        cw1 = wwx * (y - y0f);
    }

    // ---- Phase B (consumer) ----
    const int cidx  = (lane >> 2) & 3;
    const int slot  = cidx & 1;               // lane-constant
    const int obase = ((lane >> 4) << 1) | (cidx >> 1);  // owner = 4i + obase
    const unsigned qoff = (unsigned)(q * 16);

    float acc[8];
#pragma unroll
    for (int j = 0; j < 8; j++) acc[j] = 0.0f;

#pragma unroll
    for (int g = 0; g < 2; g++) {
        unsigned offs[4];
        float    cwv[4];
#pragma unroll
        for (int j = 0; j < 4; j++) {
            const int i = g * 4 + j;
            const int owner = i * 4 + obase;
            const unsigned o0 = __shfl_sync(~0u, offs0, owner);
            const unsigned o1 = __shfl_sync(~0u, offs1, owner);
            const float    c0 = __shfl_sync(~0u, cw0,   owner);
            const float    c1s = __shfl_sync(~0u, cw1,  owner);
            offs[j] = (slot ? o1 : o0) + qoff;
            cwv[j]  = slot ? c1s : c0;
        }

        uint4 hv[4];
#pragma unroll
        for (int j = 0; j < 4; j++)
            hv[j] = __ldg((const uint4*)(vbase + offs[j]));

#pragma unroll
        for (int j = 0; j < 4; j++) {
            const float cw = cwv[j];
            const float2 f0 = __half22float2(*(const __half2*)&hv[j].x);
            const float2 f1 = __half22float2(*(const __half2*)&hv[j].y);
            const float2 f2 = __half22float2(*(const __half2*)&hv[j].z);
            const float2 f3 = __half22float2(*(const __half2*)&hv[j].w);
            acc[0] = fmaf(cw, f0.x, acc[0]);
            acc[1] = fmaf(cw, f0.y, acc[1]);
            acc[2] = fmaf(cw, f1.x, acc[2]);
            acc[3] = fmaf(cw, f1.y, acc[3]);
            acc[4] = fmaf(cw, f2.x, acc[4]);
            acc[5] = fmaf(cw, f2.y, acc[5]);
            acc[6] = fmaf(cw, f3.x, acc[6]);
            acc[7] = fmaf(cw, f3.y, acc[7]);
        }
    }

    // reduce across the 8 units (lanes q, q+4, ..., q+28)
#pragma unroll
    for (int m = 4; m <= 16; m <<= 1)
#pragma unroll
        for (int j = 0; j < 8; j++)
            acc[j] += __shfl_xor_sync(~0u, acc[j], m);

    if ((lane >> 2) == 0) {
        float* dst = g_mid + (size_t)bq * 256 + h * 32 + q * 8;
        *(float4*)(dst + 0) = make_float4(acc[0], acc[1], acc[2], acc[3]);
        *(float4*)(dst + 4) = make_float4(acc[4], acc[5], acc[6], acc[7]);
    }
}

// ---------------------------------------------------------------------------
// launch
// ---------------------------------------------------------------------------
extern "C" void kernel_launch(void* const* d_in, const int* in_sizes, int n_in,
                              void* d_out, int out_size)
{
    const float* query = (const float*)d_in[0];
    const float* value = (const float*)d_in[1];
    const float* refp  = (const float*)d_in[2];
    const float* Wv    = (const float*)d_in[3];
    const float* bv    = (const float*)d_in[4];
    const float* Woff  = (const float*)d_in[5];
    const float* boff  = (const float*)d_in[6];
    const float* Wa    = (const float*)d_in[7];
    const float* ba    = (const float*)d_in[8];
    const float* Wout  = (const float*)d_in[9];
    const float* bout  = (const float*)d_in[10];
    float* out = (float*)d_out;

    float *pAw, *pMid;
    cudaGetSymbolAddress((void**)&pAw,  g_aw);
    cudaGetSymbolAddress((void**)&pMid, g_mid);

    const dim3 gN256(2, MROWS / 128);   // (2, 340)
    const dim3 gOffAw(3, MROWS / 128);  // (3, 340)

    tf32gemm<<<gN256, 256>>>(value, Wv, bv, /*unused in mode1*/ pMid, 256, 1);
    tf32gemm_offaw<<<gOffAw, 256>>>(query, Woff, boff, Wa, ba);
    softmax2_kernel<<<MROWS / 8, 256>>>(pAw);
    msdeform_sample_kernel<<<MROWS, 256>>>(refp);
    tf32gemm<<<gN256, 256>>>(pMid, Wout, bout, out, 256, 0);
}

// round 12
// speedup vs baseline: 1.2834x; 1.0207x over previous
#include <cuda_runtime.h>
#include <cuda_fp16.h>

// ---------------------------------------------------------------------------
// MSDeformAttention  (bs=8, Lq=Lv=5440, D=256, 8 heads x 32, 4 levels x 4 pts)
//
//   1) V      = value @ Wv + bv    (tf32 MMA; epilogue -> fp16 x-PAIR layout)
//   2) OFF/AW = query @ [Woff|Wa]  (single fused tf32 MMA launch)
//   3) AW     = softmax16(softmax128(AWL))
//   4) MID    = bilinear-gather v7 (pair-entry loads: 2 aligned 128B/point)
//   5) out    = MID @ Wout + bout  (tf32 MMA)
//
// Pair layout: entry(y,x) = [V(y,x,0..31) | V(y,min(x+1,S-1),0..31)]  (128 B)
// => each bilinear point reads exactly 2 aligned cache lines.
// ---------------------------------------------------------------------------

#define LQ     5440
#define BSZ    8
#define NH     8
#define DH     32
#define DMODEL 256
#define MROWS  (BSZ * LQ)          // 43520
#define KDIM   256

// scratch (static device globals: allocation-free)
__device__ __align__(128) __half g_Vp[(size_t)BSZ * NH * LQ * 64];  // pair layout
__device__ float  g_off[(size_t)MROWS * DMODEL];
__device__ float  g_aw [(size_t)MROWS * 128];
__device__ float  g_mid[(size_t)MROWS * DMODEL];

// tf32 round (rna); returns the b32 bit pattern (cvt.rna.tf32 needs .b32 dst).
__device__ __forceinline__ unsigned f2tf32(float x) {
    unsigned y;
    asm("cvt.rna.tf32.f32 %0, %1;" : "=r"(y) : "f"(x));
    return y;
}

// decode pos (0..5439) -> x within its level row, and S
__device__ __forceinline__ void decode_x(int pos, int& x, int& S) {
    int pil;
    if (pos < 4096)      { pil = pos;        S = 64; }
    else if (pos < 5120) { pil = pos - 4096; S = 32; }
    else if (pos < 5376) { pil = pos - 5120; S = 16; }
    else                 { pil = pos - 5376; S = 8;  }
    x = pil & (S - 1);
}

// ---------------------------------------------------------------------------
// Shared GEMM body: C[M,N] = A[M,256] @ B[256,N] + bias[N]
// Block tile 128x128, BK=16, 256 threads = 8 warps (4m x 2n), warp tile 32x64.
// Software-pipelined (register prefetch of next k-tile).
// mode 0: row-major fp32 C.   mode 1: fp16 dual-store into g_Vp pair layout.
// ---------------------------------------------------------------------------
__device__ __forceinline__ void gemm_body(
    const float* __restrict__ A, const float* __restrict__ B,
    const float* __restrict__ bias, float* __restrict__ C,
    int N, int m0, int n0, int mode)
{
    __shared__ unsigned As[16][136];   // [k][m]  (tf32 bit patterns)
    __shared__ unsigned Bs[16][136];   // [k][n]

    const int tid  = threadIdx.x;
    const int lane = tid & 31;
    const int warp = tid >> 5;
    const int gid  = lane >> 2;     // 0..7
    const int tig  = lane & 3;      // 0..3
    const int wm   = (warp >> 1) * 32;
    const int wn   = (warp & 1) * 64;

    const int la_row = tid >> 1;
    const int la_cg  = (tid & 1) * 8;
    const int lb_row = tid >> 4;
    const int lb_c4  = (tid & 15) * 4;

    const float* Ap = A + (size_t)(m0 + la_row) * KDIM + la_cg;
    const float* Bp = B + (size_t)lb_row * N + n0 + lb_c4;

    float acc[2][8][4];
#pragma unroll
    for (int mt = 0; mt < 2; mt++)
#pragma unroll
        for (int nt = 0; nt < 8; nt++)
#pragma unroll
            for (int r = 0; r < 4; r++) acc[mt][nt][r] = 0.0f;

    float4 av0 = *(const float4*)(Ap);
    float4 av1 = *(const float4*)(Ap + 4);
    float4 bv0 = *(const float4*)(Bp);
    float4 bv1 = *(const float4*)(Bp + 64);

    for (int k0 = 0; k0 < KDIM; k0 += 16) {
        As[la_cg + 0][la_row] = f2tf32(av0.x);
        As[la_cg + 1][la_row] = f2tf32(av0.y);
        As[la_cg + 2][la_row] = f2tf32(av0.z);
        As[la_cg + 3][la_row] = f2tf32(av0.w);
        As[la_cg + 4][la_row] = f2tf32(av1.x);
        As[la_cg + 5][la_row] = f2tf32(av1.y);
        As[la_cg + 6][la_row] = f2tf32(av1.z);
        As[la_cg + 7][la_row] = f2tf32(av1.w);
        Bs[lb_row][lb_c4 + 0]  = f2tf32(bv0.x);
        Bs[lb_row][lb_c4 + 1]  = f2tf32(bv0.y);
        Bs[lb_row][lb_c4 + 2]  = f2tf32(bv0.z);
        Bs[lb_row][lb_c4 + 3]  = f2tf32(bv0.w);
        Bs[lb_row][lb_c4 + 64] = f2tf32(bv1.x);
        Bs[lb_row][lb_c4 + 65] = f2tf32(bv1.y);
        Bs[lb_row][lb_c4 + 66] = f2tf32(bv1.z);
        Bs[lb_row][lb_c4 + 67] = f2tf32(bv1.w);
        __syncthreads();

        if (k0 + 16 < KDIM) {
            Ap += 16;
            Bp += (size_t)16 * N;
            av0 = *(const float4*)(Ap);
            av1 = *(const float4*)(Ap + 4);
            bv0 = *(const float4*)(Bp);
            bv1 = *(const float4*)(Bp + 64);
        }

#pragma unroll
        for (int ks = 0; ks < 16; ks += 8) {
            unsigned a[2][4], b[8][2];
#pragma unroll
            for (int mt = 0; mt < 2; mt++) {
                const int mb = wm + mt * 16;
                a[mt][0] = As[ks + tig    ][mb + gid    ];
                a[mt][1] = As[ks + tig    ][mb + gid + 8];
                a[mt][2] = As[ks + tig + 4][mb + gid    ];
                a[mt][3] = As[ks + tig + 4][mb + gid + 8];
            }
#pragma unroll
            for (int nt = 0; nt < 8; nt++) {
                const int nb = wn + nt * 8 + gid;
                b[nt][0] = Bs[ks + tig    ][nb];
                b[nt][1] = Bs[ks + tig + 4][nb];
            }
#pragma unroll
            for (int mt = 0; mt < 2; mt++)
#pragma unroll
                for (int nt = 0; nt < 8; nt++) {
                    asm volatile(
                        "mma.sync.aligned.m16n8k8.row.col.f32.tf32.tf32.f32 "
                        "{%0,%1,%2,%3}, {%4,%5,%6,%7}, {%8,%9}, {%0,%1,%2,%3};"
                        : "+f"(acc[mt][nt][0]), "+f"(acc[mt][nt][1]),
                          "+f"(acc[mt][nt][2]), "+f"(acc[mt][nt][3])
                        : "r"(a[mt][0]), "r"(a[mt][1]), "r"(a[mt][2]), "r"(a[mt][3]),
                          "r"(b[nt][0]), "r"(b[nt][1]));
                }
        }
        __syncthreads();
    }

    // epilogue
#pragma unroll
    for (int mt = 0; mt < 2; mt++) {
#pragma unroll
        for (int rr = 0; rr < 2; rr++) {
            const int m = m0 + wm + mt * 16 + gid + rr * 8;
            const int bb  = m / LQ;
            const int pos = m - bb * LQ;

            int xcol = 0, S = 0;
            size_t rowbase = 0;
            if (mode == 1) {
                decode_x(pos, xcol, S);
                rowbase = ((size_t)(bb * NH) * LQ + pos) * 64;  // +h*LQ*64 later
            }
#pragma unroll
            for (int nt = 0; nt < 8; nt++) {
                const int n = n0 + wn + nt * 8 + tig * 2;
                float2 v;
                v.x = acc[mt][nt][rr * 2 + 0] + bias[n];
                v.y = acc[mt][nt][rr * 2 + 1] + bias[n + 1];
                if (mode == 0) {
                    *(float2*)&C[(size_t)m * N + n] = v;
                } else {
                    const int h = n >> 5;
                    const int c = n & 31;   // even
                    const __half2 hv = __floats2half2_rn(v.x, v.y);
                    const size_t base = rowbase + (size_t)h * LQ * 64;
                    // lo half of entry(y,x)
                    *(__half2*)&g_Vp[base + c] = hv;
                    // hi half of entry(y,x-1) = V(y,x)
                    if (xcol > 0)
                        *(__half2*)&g_Vp[base - 64 + 32 + c] = hv;
                    // boundary self-duplicate: entry(y,S-1).hi = V(y,S-1)
                    if (xcol == S - 1)
                        *(__half2*)&g_Vp[base + 32 + c] = hv;
                }
            }
        }
    }
}

// generic GEMM kernel (used for V and final output)
__global__ __launch_bounds__(256) void tf32gemm(
    const float* __restrict__ A, const float* __restrict__ B,
    const float* __restrict__ bias, float* __restrict__ C,
    int N, int mode)
{
    gemm_body(A, B, bias, C, N, blockIdx.y * 128, blockIdx.x * 128, mode);
}

// fused OFF + AW GEMM: grid.x = 3.  Blocks 0,1 -> query@Woff -> g_off (N=256);
// block 2 -> query@Wa -> g_aw (N=128).
__global__ __launch_bounds__(256) void tf32gemm_offaw(
    const float* __restrict__ A,
    const float* __restrict__ Woff, const float* __restrict__ boff,
    const float* __restrict__ Wa,   const float* __restrict__ ba)
{
    const int m0 = blockIdx.y * 128;
    if (blockIdx.x < 2) {
        gemm_body(A, Woff, boff, g_off, 256, m0, blockIdx.x * 128, 0);
    } else {
        gemm_body(A, Wa, ba, g_aw, 128, m0, 0, 0);
    }
}

// ---------------------------------------------------------------------------
// Double softmax (unchanged).
// ---------------------------------------------------------------------------
__global__ __launch_bounds__(256) void softmax2_kernel(float* __restrict__ buf)
{
    const int warp = threadIdx.x >> 5;
    const int lane = threadIdx.x & 31;
    const int row  = blockIdx.x * 8 + warp;
    float* p = buf + (size_t)row * 128 + lane * 4;

    float4 v = *(const float4*)p;

    float vm = fmaxf(fmaxf(v.x, v.y), fmaxf(v.z, v.w));
#pragma unroll
    for (int o = 16; o; o >>= 1) vm = fmaxf(vm, __shfl_xor_sync(~0u, vm, o));
    float e0 = expf(v.x - vm), e1 = expf(v.y - vm);
    float e2 = expf(v.z - vm), e3 = expf(v.w - vm);
    float s = e0 + e1 + e2 + e3;
#pragma unroll
    for (int o = 16; o; o >>= 1) s += __shfl_xor_sync(~0u, s, o);
    const float inv = 1.0f / s;
    const float t0 = e0 * inv, t1 = e1 * inv, t2 = e2 * inv, t3 = e3 * inv;

    float gm = fmaxf(fmaxf(t0, t1), fmaxf(t2, t3));
    gm = fmaxf(gm, __shfl_xor_sync(~0u, gm, 1));
    gm = fmaxf(gm, __shfl_xor_sync(~0u, gm, 2));
    float f0 = expf(t0 - gm), f1 = expf(t1 - gm);
    float f2 = expf(t2 - gm), f3 = expf(t3 - gm);
    float gs = f0 + f1 + f2 + f3;
    gs += __shfl_xor_sync(~0u, gs, 1);
    gs += __shfl_xor_sync(~0u, gs, 2);
    const float ginv = 1.0f / gs;

    float4 o4;
    o4.x = f0 * ginv; o4.y = f1 * ginv; o4.z = f2 * ginv; o4.w = f3 * ginv;
    *(float4*)p = o4;
}

// ---------------------------------------------------------------------------
// Sampling v7: pair-entry loads.
//
// Producer: lane l owns (point p = l>>1, ypair z = l&1) and emits
//   offs  = byte offset of pair entry(y_z, x0c)   (one aligned 128B line)
//   cwlo  = w * (x1f-x) * wy_z      (weight for entry .lo = V(y_z, x0c))
//   cwhi  = w * (x-x0f) * wy_z      (weight for entry .hi = V(y_z, x1c))
//
// Consumer: lane = (pu = lane>>3, e = lane&7).  Pass i: slot pu handles
// (point 2i + (pu>>1), ypair pu&1); owner = 4i + 2*(pu>>1) + (pu&1).
// e selects the 16B chunk: e<4 -> .lo (x0) chans (e&3)*8, e>=4 -> .hi (x1)
// same chans.  8 LDG.128 total; each instruction touches 4 aligned lines.
// Channels of lane = (lane&3)*8..+7; reduction over xor 4,8,16 as before.
// ---------------------------------------------------------------------------
__global__ __launch_bounds__(256, 4) void msdeform_sample_kernel(
    const float* __restrict__ refpts)
{
    const int bq   = blockIdx.x;
    const int b    = bq / LQ;
    const int h    = threadIdx.x >> 5;
    const int lane = threadIdx.x & 31;
    const int q    = lane & 3;        // channel quarter

    const float2* offp2 = (const float2*)(g_off + (size_t)bq * 256 + h * 32);
    const float*  awp   = g_aw + (size_t)bq * 128 + h * 16;
    const float*  refp  = refpts + (size_t)bq * 8;
    const char*   vbase = (const char*)(g_Vp + ((size_t)(b * NH + h)) * LQ * 64);

    // ---- Producer: point = lane>>1, ypair z = lane&1 ----
    unsigned offs_p;
    float cwlo_p, cwhi_p;
    {
        const int own_p = lane >> 1;          // point 0..15
        const int z     = lane & 1;           // y side
        const int l     = own_p >> 2;         // level 0..3
        const int S     = 64 >> l;
        const int start = (16384 - ((S * S) << 2)) / 3;   // 0,4096,5120,5376
        const float inv_S = __int_as_float((121 + l) << 23);  // exact 1/S
        const float c1  = 0.5f * (float)S - 1.0f;             // 0.5*(S-2)
        const float a   = c1 * inv_S;                         // exact

        const float2 r = __ldg((const float2*)(refp + l * 2));
        const float2 o = __ldg(&offp2[own_p]);
        const float  w = __ldg(&awp[own_p]);

        const float x = fmaf(o.x, a, fmaf(r.x, c1, c1));
        const float y = fmaf(o.y, a, fmaf(r.y, c1, c1));

        const int x0 = (int)floorf(x);
        const int y0 = (int)floorf(y);
        const int x0c = min(max(x0, 0),     S - 1);
        const int y0c = min(max(y0, 0),     S - 1);
        const int y1c = min(max(y0 + 1, 0), S - 1);
        const float x0f = (float)x0c;
        const float x1f = (float)min(max(x0 + 1, 0), S - 1);
        const float y0f = (float)y0c, y1f = (float)y1c;

        const int   ysel = z ? y1c : y0c;
        const float wy   = z ? (y - y0f) : (y1f - y);
        const float wwy  = w;    // keep association (w*wx)*wy as before:
        const float wxlo = (x1f - x);
        const float wxhi = (x - x0f);

        offs_p  = (unsigned)((start + ysel * S + x0c) << 7);   // *128 bytes
        cwlo_p  = (wwy * wxlo) * wy;
        cwhi_p  = (wwy * wxhi) * wy;
    }

    // ---- Consumer ----
    const int pu   = lane >> 3;               // pair-slot 0..3
    const int e    = lane & 7;                // 16B chunk in the pair entry
    const int ehi  = e >> 2;                  // 0 = .lo (x0), 1 = .hi (x1)
    const int obase = ((pu >> 1) << 1) | (pu & 1);   // 2*psel + yp
    const unsigned eoff = (unsigned)(e * 16);

    float acc[8];
#pragma unroll
    for (int j = 0; j < 8; j++) acc[j] = 0.0f;

#pragma unroll
    for (int g = 0; g < 2; g++) {
        unsigned offs[4];
        float    cwv[4];
#pragma unroll
        for (int j = 0; j < 4; j++) {
            const int i = g * 4 + j;
            const int owner = i * 4 + obase;
            const unsigned o_ = __shfl_sync(~0u, offs_p, owner);
            const float    cl = __shfl_sync(~0u, cwlo_p, owner);
            const float    ch = __shfl_sync(~0u, cwhi_p, owner);
            offs[j] = o_ + eoff;
            cwv[j]  = ehi ? ch : cl;
        }

        uint4 hv[4];
#pragma unroll
        for (int j = 0; j < 4; j++)
            hv[j] = __ldg((const uint4*)(vbase + offs[j]));

#pragma unroll
        for (int j = 0; j < 4; j++) {
            const float cw = cwv[j];
            const float2 f0 = __half22float2(*(const __half2*)&hv[j].x);
            const float2 f1 = __half22float2(*(const __half2*)&hv[j].y);
            const float2 f2 = __half22float2(*(const __half2*)&hv[j].z);
            const float2 f3 = __half22float2(*(const __half2*)&hv[j].w);
            acc[0] = fmaf(cw, f0.x, acc[0]);
            acc[1] = fmaf(cw, f0.y, acc[1]);
            acc[2] = fmaf(cw, f1.x, acc[2]);
            acc[3] = fmaf(cw, f1.y, acc[3]);
            acc[4] = fmaf(cw, f2.x, acc[4]);
            acc[5] = fmaf(cw, f2.y, acc[5]);
            acc[6] = fmaf(cw, f3.x, acc[6]);
            acc[7] = fmaf(cw, f3.y, acc[7]);
        }
    }

    // reduce across the 8 lanes sharing this q (lanes q, q+4, ..., q+28)
#pragma unroll
    for (int m = 4; m <= 16; m <<= 1)
#pragma unroll
        for (int j = 0; j < 8; j++)
            acc[j] += __shfl_xor_sync(~0u, acc[j], m);

    if ((lane >> 2) == 0) {
        float* dst = g_mid + (size_t)bq * 256 + h * 32 + q * 8;
        *(float4*)(dst + 0) = make_float4(acc[0], acc[1], acc[2], acc[3]);
        *(float4*)(dst + 4) = make_float4(acc[4], acc[5], acc[6], acc[7]);
    }
}

// ---------------------------------------------------------------------------
// launch
// ---------------------------------------------------------------------------
extern "C" void kernel_launch(void* const* d_in, const int* in_sizes, int n_in,
                              void* d_out, int out_size)
{
    const float* query = (const float*)d_in[0];
    const float* value = (const float*)d_in[1];
    const float* refp  = (const float*)d_in[2];
    const float* Wv    = (const float*)d_in[3];
    const float* bv    = (const float*)d_in[4];
    const float* Woff  = (const float*)d_in[5];
    const float* boff  = (const float*)d_in[6];
    const float* Wa    = (const float*)d_in[7];
    const float* ba    = (const float*)d_in[8];
    const float* Wout  = (const float*)d_in[9];
    const float* bout  = (const float*)d_in[10];
    float* out = (float*)d_out;

    float *pAw, *pMid;
    cudaGetSymbolAddress((void**)&pAw,  g_aw);
    cudaGetSymbolAddress((void**)&pMid, g_mid);

    const dim3 gN256(2, MROWS / 128);   // (2, 340)
    const dim3 gOffAw(3, MROWS / 128);  // (3, 340)

    tf32gemm<<<gN256, 256>>>(value, Wv, bv, /*unused in mode1*/ pMid, 256, 1);
    tf32gemm_offaw<<<gOffAw, 256>>>(query, Woff, boff, Wa, ba);
    softmax2_kernel<<<MROWS / 8, 256>>>(pAw);
    msdeform_sample_kernel<<<MROWS, 256>>>(refp);
    tf32gemm<<<gN256, 256>>>(pMid, Wout, bout, out, 256, 0);
}

// round 13
// speedup vs baseline: 1.3454x; 1.0483x over previous
#include <cuda_runtime.h>
#include <cuda_fp16.h>

// ---------------------------------------------------------------------------
// MSDeformAttention  (bs=8, Lq=Lv=5440, D=256, 8 heads x 32, 4 levels x 4 pts)
//
//   1) V      = value @ Wv + bv    (tf32 MMA; epilogue -> fp16 x-PAIR layout)
//   2) OFF/AW = query @ [Woff|Wa]  (single fused tf32 MMA launch)
//   3) AW     = softmax16(softmax128(AWL))
//   4) MID    = bilinear-gather v7 (pair-entry loads: 2 aligned 128B/point)
//   5) out    = MID @ Wout + bout  (tf32 MMA)
//
// R13: occupancy push — GEMMs forced to 2 CTAs/SM (were reg-capped at 1),
//      sampler forced to 5 CTAs/SM (was 4).
// ---------------------------------------------------------------------------

#define LQ     5440
#define BSZ    8
#define NH     8
#define DH     32
#define DMODEL 256
#define MROWS  (BSZ * LQ)          // 43520
#define KDIM   256

// scratch (static device globals: allocation-free)
__device__ __align__(128) __half g_Vp[(size_t)BSZ * NH * LQ * 64];  // pair layout
__device__ float  g_off[(size_t)MROWS * DMODEL];
__device__ float  g_aw [(size_t)MROWS * 128];
__device__ float  g_mid[(size_t)MROWS * DMODEL];

// tf32 round (rna); returns the b32 bit pattern (cvt.rna.tf32 needs .b32 dst).
__device__ __forceinline__ unsigned f2tf32(float x) {
    unsigned y;
    asm("cvt.rna.tf32.f32 %0, %1;" : "=r"(y) : "f"(x));
    return y;
}

// decode pos (0..5439) -> x within its level row, and S
__device__ __forceinline__ void decode_x(int pos, int& x, int& S) {
    int pil;
    if (pos < 4096)      { pil = pos;        S = 64; }
    else if (pos < 5120) { pil = pos - 4096; S = 32; }
    else if (pos < 5376) { pil = pos - 5120; S = 16; }
    else                 { pil = pos - 5376; S = 8;  }
    x = pil & (S - 1);
}

// ---------------------------------------------------------------------------
// Shared GEMM body: C[M,N] = A[M,256] @ B[256,N] + bias[N]
// Block tile 128x128, BK=16, 256 threads = 8 warps (4m x 2n), warp tile 32x64.
// Software-pipelined (register prefetch of next k-tile).
// mode 0: row-major fp32 C.   mode 1: fp16 dual-store into g_Vp pair layout.
// ---------------------------------------------------------------------------
__device__ __forceinline__ void gemm_body(
    const float* __restrict__ A, const float* __restrict__ B,
    const float* __restrict__ bias, float* __restrict__ C,
    int N, int m0, int n0, int mode)
{
    __shared__ unsigned As[16][136];   // [k][m]  (tf32 bit patterns)
    __shared__ unsigned Bs[16][136];   // [k][n]

    const int tid  = threadIdx.x;
    const int lane = tid & 31;
    const int warp = tid >> 5;
    const int gid  = lane >> 2;     // 0..7
    const int tig  = lane & 3;      // 0..3
    const int wm   = (warp >> 1) * 32;
    const int wn   = (warp & 1) * 64;

    const int la_row = tid >> 1;
    const int la_cg  = (tid & 1) * 8;
    const int lb_row = tid >> 4;
    const int lb_c4  = (tid & 15) * 4;

    const float* Ap = A + (size_t)(m0 + la_row) * KDIM + la_cg;
    const float* Bp = B + (size_t)lb_row * N + n0 + lb_c4;

    float acc[2][8][4];
#pragma unroll
    for (int mt = 0; mt < 2; mt++)
#pragma unroll
        for (int nt = 0; nt < 8; nt++)
#pragma unroll
            for (int r = 0; r < 4; r++) acc[mt][nt][r] = 0.0f;

    float4 av0 = *(const float4*)(Ap);
    float4 av1 = *(const float4*)(Ap + 4);
    float4 bv0 = *(const float4*)(Bp);
    float4 bv1 = *(const float4*)(Bp + 64);

    for (int k0 = 0; k0 < KDIM; k0 += 16) {
        As[la_cg + 0][la_row] = f2tf32(av0.x);
        As[la_cg + 1][la_row] = f2tf32(av0.y);
        As[la_cg + 2][la_row] = f2tf32(av0.z);
        As[la_cg + 3][la_row] = f2tf32(av0.w);
        As[la_cg + 4][la_row] = f2tf32(av1.x);
        As[la_cg + 5][la_row] = f2tf32(av1.y);
        As[la_cg + 6][la_row] = f2tf32(av1.z);
        As[la_cg + 7][la_row] = f2tf32(av1.w);
        Bs[lb_row][lb_c4 + 0]  = f2tf32(bv0.x);
        Bs[lb_row][lb_c4 + 1]  = f2tf32(bv0.y);
        Bs[lb_row][lb_c4 + 2]  = f2tf32(bv0.z);
        Bs[lb_row][lb_c4 + 3]  = f2tf32(bv0.w);
        Bs[lb_row][lb_c4 + 64] = f2tf32(bv1.x);
        Bs[lb_row][lb_c4 + 65] = f2tf32(bv1.y);
        Bs[lb_row][lb_c4 + 66] = f2tf32(bv1.z);
        Bs[lb_row][lb_c4 + 67] = f2tf32(bv1.w);
        __syncthreads();

        if (k0 + 16 < KDIM) {
            Ap += 16;
            Bp += (size_t)16 * N;
            av0 = *(const float4*)(Ap);
            av1 = *(const float4*)(Ap + 4);
            bv0 = *(const float4*)(Bp);
            bv1 = *(const float4*)(Bp + 64);
        }

#pragma unroll
        for (int ks = 0; ks < 16; ks += 8) {
            unsigned a[2][4], b[8][2];
#pragma unroll
            for (int mt = 0; mt < 2; mt++) {
                const int mb = wm + mt * 16;
                a[mt][0] = As[ks + tig    ][mb + gid    ];
                a[mt][1] = As[ks + tig    ][mb + gid + 8];
                a[mt][2] = As[ks + tig + 4][mb + gid    ];
                a[mt][3] = As[ks + tig + 4][mb + gid + 8];
            }
#pragma unroll
            for (int nt = 0; nt < 8; nt++) {
                const int nb = wn + nt * 8 + gid;
                b[nt][0] = Bs[ks + tig    ][nb];
                b[nt][1] = Bs[ks + tig + 4][nb];
            }
#pragma unroll
            for (int mt = 0; mt < 2; mt++)
#pragma unroll
                for (int nt = 0; nt < 8; nt++) {
                    asm volatile(
                        "mma.sync.aligned.m16n8k8.row.col.f32.tf32.tf32.f32 "
                        "{%0,%1,%2,%3}, {%4,%5,%6,%7}, {%8,%9}, {%0,%1,%2,%3};"
                        : "+f"(acc[mt][nt][0]), "+f"(acc[mt][nt][1]),
                          "+f"(acc[mt][nt][2]), "+f"(acc[mt][nt][3])
                        : "r"(a[mt][0]), "r"(a[mt][1]), "r"(a[mt][2]), "r"(a[mt][3]),
                          "r"(b[nt][0]), "r"(b[nt][1]));
                }
        }
        __syncthreads();
    }

    // epilogue
#pragma unroll
    for (int mt = 0; mt < 2; mt++) {
#pragma unroll
        for (int rr = 0; rr < 2; rr++) {
            const int m = m0 + wm + mt * 16 + gid + rr * 8;
            const int bb  = m / LQ;
            const int pos = m - bb * LQ;

            int xcol = 0, S = 0;
            size_t rowbase = 0;
            if (mode == 1) {
                decode_x(pos, xcol, S);
                rowbase = ((size_t)(bb * NH) * LQ + pos) * 64;  // +h*LQ*64 later
            }
#pragma unroll
            for (int nt = 0; nt < 8; nt++) {
                const int n = n0 + wn + nt * 8 + tig * 2;
                float2 v;
                v.x = acc[mt][nt][rr * 2 + 0] + bias[n];
                v.y = acc[mt][nt][rr * 2 + 1] + bias[n + 1];
                if (mode == 0) {
                    *(float2*)&C[(size_t)m * N + n] = v;
                } else {
                    const int h = n >> 5;
                    const int c = n & 31;   // even
                    const __half2 hv = __floats2half2_rn(v.x, v.y);
                    const size_t base = rowbase + (size_t)h * LQ * 64;
                    // lo half of entry(y,x)
                    *(__half2*)&g_Vp[base + c] = hv;
                    // hi half of entry(y,x-1) = V(y,x)
                    if (xcol > 0)
                        *(__half2*)&g_Vp[base - 64 + 32 + c] = hv;
                    // boundary self-duplicate: entry(y,S-1).hi = V(y,S-1)
                    if (xcol == S - 1)
                        *(__half2*)&g_Vp[base + 32 + c] = hv;
                }
            }
        }
    }
}

// generic GEMM kernel (used for V and final output)
// __launch_bounds__(256,2): cap regs at 128 so 2 CTAs co-reside per SM and
// overlap each other's syncthreads / epilogue bubbles.
__global__ __launch_bounds__(256, 2) void tf32gemm(
    const float* __restrict__ A, const float* __restrict__ B,
    const float* __restrict__ bias, float* __restrict__ C,
    int N, int mode)
{
    gemm_body(A, B, bias, C, N, blockIdx.y * 128, blockIdx.x * 128, mode);
}

// fused OFF + AW GEMM: grid.x = 3.  Blocks 0,1 -> query@Woff -> g_off (N=256);
// block 2 -> query@Wa -> g_aw (N=128).
__global__ __launch_bounds__(256, 2) void tf32gemm_offaw(
    const float* __restrict__ A,
    const float* __restrict__ Woff, const float* __restrict__ boff,
    const float* __restrict__ Wa,   const float* __restrict__ ba)
{
    const int m0 = blockIdx.y * 128;
    if (blockIdx.x < 2) {
        gemm_body(A, Woff, boff, g_off, 256, m0, blockIdx.x * 128, 0);
    } else {
        gemm_body(A, Wa, ba, g_aw, 128, m0, 0, 0);
    }
}

// ---------------------------------------------------------------------------
// Double softmax (unchanged).
// ---------------------------------------------------------------------------
__global__ __launch_bounds__(256) void softmax2_kernel(float* __restrict__ buf)
{
    const int warp = threadIdx.x >> 5;
    const int lane = threadIdx.x & 31;
    const int row  = blockIdx.x * 8 + warp;
    float* p = buf + (size_t)row * 128 + lane * 4;

    float4 v = *(const float4*)p;

    float vm = fmaxf(fmaxf(v.x, v.y), fmaxf(v.z, v.w));
#pragma unroll
    for (int o = 16; o; o >>= 1) vm = fmaxf(vm, __shfl_xor_sync(~0u, vm, o));
    float e0 = expf(v.x - vm), e1 = expf(v.y - vm);
    float e2 = expf(v.z - vm), e3 = expf(v.w - vm);
    float s = e0 + e1 + e2 + e3;
#pragma unroll
    for (int o = 16; o; o >>= 1) s += __shfl_xor_sync(~0u, s, o);
    const float inv = 1.0f / s;
    const float t0 = e0 * inv, t1 = e1 * inv, t2 = e2 * inv, t3 = e3 * inv;

    float gm = fmaxf(fmaxf(t0, t1), fmaxf(t2, t3));
    gm = fmaxf(gm, __shfl_xor_sync(~0u, gm, 1));
    gm = fmaxf(gm, __shfl_xor_sync(~0u, gm, 2));
    float f0 = expf(t0 - gm), f1 = expf(t1 - gm);
    float f2 = expf(t2 - gm), f3 = expf(t3 - gm);
    float gs = f0 + f1 + f2 + f3;
    gs += __shfl_xor_sync(~0u, gs, 1);
    gs += __shfl_xor_sync(~0u, gs, 2);
    const float ginv = 1.0f / gs;

    float4 o4;
    o4.x = f0 * ginv; o4.y = f1 * ginv; o4.z = f2 * ginv; o4.w = f3 * ginv;
    *(float4*)p = o4;
}

// ---------------------------------------------------------------------------
// Sampling v7 (pair-entry loads), now at 5 CTAs/SM.
//
// Producer: lane l owns (point p = l>>1, ypair z = l&1) and emits
//   offs = byte offset of pair entry(y_z, x0c) (one aligned 128B line),
//   cwlo/cwhi = weights for .lo (x0) / .hi (x1) halves.
// Consumer: lane = (pu = lane>>3, e = lane&7).  Pass i: owner =
// 4i + 2*(pu>>1) + (pu&1); e selects the 16B chunk (e<4 -> .lo, e>=4 -> .hi).
// 8 LDG.128 total; each instruction touches 4 aligned lines.
// ---------------------------------------------------------------------------
__global__ __launch_bounds__(256, 5) void msdeform_sample_kernel(
    const float* __restrict__ refpts)
{
    const int bq   = blockIdx.x;
    const int b    = bq / LQ;
    const int h    = threadIdx.x >> 5;
    const int lane = threadIdx.x & 31;
    const int q    = lane & 3;        // channel quarter

    const float2* offp2 = (const float2*)(g_off + (size_t)bq * 256 + h * 32);
    const float*  awp   = g_aw + (size_t)bq * 128 + h * 16;
    const float*  refp  = refpts + (size_t)bq * 8;
    const char*   vbase = (const char*)(g_Vp + ((size_t)(b * NH + h)) * LQ * 64);

    // ---- Producer: point = lane>>1, ypair z = lane&1 ----
    unsigned offs_p;
    float cwlo_p, cwhi_p;
    {
        const int own_p = lane >> 1;          // point 0..15
        const int z     = lane & 1;           // y side
        const int l     = own_p >> 2;         // level 0..3
        const int S     = 64 >> l;
        const int start = (16384 - ((S * S) << 2)) / 3;   // 0,4096,5120,5376
        const float inv_S = __int_as_float((121 + l) << 23);  // exact 1/S
        const float c1  = 0.5f * (float)S - 1.0f;             // 0.5*(S-2)
        const float a   = c1 * inv_S;                         // exact

        const float2 r = __ldg((const float2*)(refp + l * 2));
        const float2 o = __ldg(&offp2[own_p]);
        const float  w = __ldg(&awp[own_p]);

        const float x = fmaf(o.x, a, fmaf(r.x, c1, c1));
        const float y = fmaf(o.y, a, fmaf(r.y, c1, c1));

        const int x0 = (int)floorf(x);
        const int y0 = (int)floorf(y);
        const int x0c = min(max(x0, 0),     S - 1);
        const int y0c = min(max(y0, 0),     S - 1);
        const int y1c = min(max(y0 + 1, 0), S - 1);
        const float x0f = (float)x0c;
        const float x1f = (float)min(max(x0 + 1, 0), S - 1);
        const float y0f = (float)y0c, y1f = (float)y1c;

        const int   ysel = z ? y1c : y0c;
        const float wy   = z ? (y - y0f) : (y1f - y);
        const float wxlo = (x1f - x);
        const float wxhi = (x - x0f);

        offs_p  = (unsigned)((start + ysel * S + x0c) << 7);   // *128 bytes
        cwlo_p  = (w * wxlo) * wy;
        cwhi_p  = (w * wxhi) * wy;
    }

    // ---- Consumer ----
    const int pu   = lane >> 3;               // pair-slot 0..3
    const int e    = lane & 7;                // 16B chunk in the pair entry
    const int ehi  = e >> 2;                  // 0 = .lo (x0), 1 = .hi (x1)
    const int obase = ((pu >> 1) << 1) | (pu & 1);   // 2*psel + yp
    const unsigned eoff = (unsigned)(e * 16);

    float acc[8];
#pragma unroll
    for (int j = 0; j < 8; j++) acc[j] = 0.0f;

#pragma unroll
    for (int g = 0; g < 2; g++) {
        unsigned offs[4];
        float    cwv[4];
#pragma unroll
        for (int j = 0; j < 4; j++) {
            const int i = g * 4 + j;
            const int owner = i * 4 + obase;
            const unsigned o_ = __shfl_sync(~0u, offs_p, owner);
            const float    cl = __shfl_sync(~0u, cwlo_p, owner);
            const float    ch = __shfl_sync(~0u, cwhi_p, owner);
            offs[j] = o_ + eoff;
            cwv[j]  = ehi ? ch : cl;
        }

        uint4 hv[4];
#pragma unroll
        for (int j = 0; j < 4; j++)
            hv[j] = __ldg((const uint4*)(vbase + offs[j]));

#pragma unroll
        for (int j = 0; j < 4; j++) {
            const float cw = cwv[j];
            const float2 f0 = __half22float2(*(const __half2*)&hv[j].x);
            const float2 f1 = __half22float2(*(const __half2*)&hv[j].y);
            const float2 f2 = __half22float2(*(const __half2*)&hv[j].z);
            const float2 f3 = __half22float2(*(const __half2*)&hv[j].w);
            acc[0] = fmaf(cw, f0.x, acc[0]);
            acc[1] = fmaf(cw, f0.y, acc[1]);
            acc[2] = fmaf(cw, f1.x, acc[2]);
            acc[3] = fmaf(cw, f1.y, acc[3]);
            acc[4] = fmaf(cw, f2.x, acc[4]);
            acc[5] = fmaf(cw, f2.y, acc[5]);
            acc[6] = fmaf(cw, f3.x, acc[6]);
            acc[7] = fmaf(cw, f3.y, acc[7]);
        }
    }

    // reduce across the 8 lanes sharing this q (lanes q, q+4, ..., q+28)
#pragma unroll
    for (int m = 4; m <= 16; m <<= 1)
#pragma unroll
        for (int j = 0; j < 8; j++)
            acc[j] += __shfl_xor_sync(~0u, acc[j], m);

    if ((lane >> 2) == 0) {
        float* dst = g_mid + (size_t)bq * 256 + h * 32 + q * 8;
        *(float4*)(dst + 0) = make_float4(acc[0], acc[1], acc[2], acc[3]);
        *(float4*)(dst + 4) = make_float4(acc[4], acc[5], acc[6], acc[7]);
    }
}

// ---------------------------------------------------------------------------
// launch
// ---------------------------------------------------------------------------
extern "C" void kernel_launch(void* const* d_in, const int* in_sizes, int n_in,
                              void* d_out, int out_size)
{
    const float* query = (const float*)d_in[0];
    const float* value = (const float*)d_in[1];
    const float* refp  = (const float*)d_in[2];
    const float* Wv    = (const float*)d_in[3];
    const float* bv    = (const float*)d_in[4];
    const float* Woff  = (const float*)d_in[5];
    const float* boff  = (const float*)d_in[6];
    const float* Wa    = (const float*)d_in[7];
    const float* ba    = (const float*)d_in[8];
    const float* Wout  = (const float*)d_in[9];
    const float* bout  = (const float*)d_in[10];
    float* out = (float*)d_out;

    float *pAw, *pMid;
    cudaGetSymbolAddress((void**)&pAw,  g_aw);
    cudaGetSymbolAddress((void**)&pMid, g_mid);

    const dim3 gN256(2, MROWS / 128);   // (2, 340)
    const dim3 gOffAw(3, MROWS / 128);  // (3, 340)

    tf32gemm<<<gN256, 256>>>(value, Wv, bv, /*unused in mode1*/ pMid, 256, 1);
    tf32gemm_offaw<<<gOffAw, 256>>>(query, Woff, boff, Wa, ba);
    softmax2_kernel<<<MROWS / 8, 256>>>(pAw);
    msdeform_sample_kernel<<<MROWS, 256>>>(refp);
    tf32gemm<<<gN256, 256>>>(pMid, Wout, bout, out, 256, 0);
}